// round 5
// baseline (speedup 1.0000x reference)
#include <cuda_runtime.h>
#include <math.h>
#include <mma.h>

using namespace nvcuda;

// Problem constants
#define NN    50000
#define NPAD  50176            // 392 * 128, so full 128-row GEMM tiles never store OOB
#define EE    1600000
#define HDIM  128

// ---------------- static device scratch (allocation-free) ----------------
__device__ __align__(16) int   g_src[EE];
__device__ __align__(16) int   g_dst[EE];
__device__ __align__(16) float g_deg[NPAD];
__device__ __align__(16) float g_dis[NPAD];
__device__ __align__(16) float g_h  [(size_t)NPAD * HDIM];
__device__ __align__(16) float g_hg [(size_t)NPAD * HDIM];
__device__ __align__(16) float g_agg[(size_t)NPAD * HDIM];

// ---------------- math helpers ----------------
__device__ __forceinline__ float mishf(float x) {
    float sp = fmaxf(x, 0.0f) + log1pf(expf(-fabsf(x)));
    return x * tanhf(sp);
}

__device__ __forceinline__ float to_tf32(float x) {
    unsigned r;
    asm("cvt.rna.tf32.f32 %0, %1;" : "=r"(r) : "f"(x));
    return __uint_as_float(r);
}

// ---------------- small kernels ----------------
__global__ void init_deg_kernel(int n) {
    int i = blockIdx.x * blockDim.x + threadIdx.x;
    if (i < n) g_deg[i] = 1.0f;   // self-loop; padded rows harmlessly stay 1
}

// edge_index arrives as int32 (JAX default x64-disabled)
__global__ void build_edges_kernel(const int* __restrict__ ei, int e, int n) {
    int i = blockIdx.x * blockDim.x + threadIdx.x;
    if (i < e) {
        int s = ei[i];
        int d = ei[e + i];
        if ((unsigned)s >= (unsigned)n) s = 0;
        if ((unsigned)d >= (unsigned)n) d = 0;
        g_src[i] = s;
        g_dst[i] = d;
        atomicAdd(&g_deg[d], 1.0f);
    }
}

__global__ void dis_kernel(int n) {
    int i = blockIdx.x * blockDim.x + threadIdx.x;
    if (i < n) g_dis[i] = rsqrtf(g_deg[i]);
}

// ---------------- 3xTF32 GEMM: C[NPAD,128] = A[:,128] @ B[128,128], raw store ----------------
// hi/lo split recovers fp32-level accuracy: D += Ahi*Bhi + Ahi*Blo + Alo*Bhi.
#define KC  16
#define LDA 20
#define LDB 132

__global__ __launch_bounds__(256) void tf32_gemm_kernel(
    const float* __restrict__ A,
    const float* __restrict__ B,
    float* __restrict__ C,
    int Mload)                       // rows of A readable; beyond -> zeros
{
    __shared__ float As_hi[128][LDA];
    __shared__ float As_lo[128][LDA];
    __shared__ float Bs_hi[KC][LDB];
    __shared__ float Bs_lo[KC][LDB];

    int tid  = threadIdx.x;
    int warp = tid >> 5;
    int wm   = warp >> 1;            // 0..3 -> 32-row band
    int wn   = warp & 1;             // 0..1 -> 64-col band
    int block_row = blockIdx.x * 128;

    wmma::fragment<wmma::accumulator, 16, 16, 8, float> c[2][4];
#pragma unroll
    for (int im = 0; im < 2; im++)
#pragma unroll
        for (int jn = 0; jn < 4; jn++) wmma::fill_fragment(c[im][jn], 0.0f);

    for (int k0 = 0; k0 < HDIM; k0 += KC) {
        // A tile: 128 x KC, split hi/lo
#pragma unroll
        for (int it = 0; it < 2; it++) {
            int idx = tid + it * 256;          // 0..511 float4 slots
            int r   = idx >> 2;
            int c4  = (idx & 3) << 2;
            float4 a = make_float4(0.f, 0.f, 0.f, 0.f);
            if (block_row + r < Mload)
                a = *reinterpret_cast<const float4*>(A + (size_t)(block_row + r) * HDIM + k0 + c4);
            float h0 = to_tf32(a.x), h1 = to_tf32(a.y), h2 = to_tf32(a.z), h3 = to_tf32(a.w);
            As_hi[r][c4 + 0] = h0;  As_lo[r][c4 + 0] = to_tf32(a.x - h0);
            As_hi[r][c4 + 1] = h1;  As_lo[r][c4 + 1] = to_tf32(a.y - h1);
            As_hi[r][c4 + 2] = h2;  As_lo[r][c4 + 2] = to_tf32(a.z - h2);
            As_hi[r][c4 + 3] = h3;  As_lo[r][c4 + 3] = to_tf32(a.w - h3);
        }
        // B tile: KC x 128, split hi/lo
#pragma unroll
        for (int it = 0; it < 2; it++) {
            int idx = tid + it * 256;
            int r   = idx >> 5;
            int cc  = (idx & 31) << 2;
            float4 b = *reinterpret_cast<const float4*>(B + (size_t)(k0 + r) * HDIM + cc);
            float h0 = to_tf32(b.x), h1 = to_tf32(b.y), h2 = to_tf32(b.z), h3 = to_tf32(b.w);
            Bs_hi[r][cc + 0] = h0;  Bs_lo[r][cc + 0] = to_tf32(b.x - h0);
            Bs_hi[r][cc + 1] = h1;  Bs_lo[r][cc + 1] = to_tf32(b.y - h1);
            Bs_hi[r][cc + 2] = h2;  Bs_lo[r][cc + 2] = to_tf32(b.z - h2);
            Bs_hi[r][cc + 3] = h3;  Bs_lo[r][cc + 3] = to_tf32(b.w - h3);
        }
        __syncthreads();

#pragma unroll
        for (int ks = 0; ks < KC / 8; ks++) {
            wmma::fragment<wmma::matrix_a, 16, 16, 8, wmma::precision::tf32, wmma::row_major> ah[2], al[2];
            wmma::fragment<wmma::matrix_b, 16, 16, 8, wmma::precision::tf32, wmma::row_major> bh[4], bl[4];
#pragma unroll
            for (int im = 0; im < 2; im++) {
                wmma::load_matrix_sync(ah[im], &As_hi[wm * 32 + im * 16][ks * 8], LDA);
                wmma::load_matrix_sync(al[im], &As_lo[wm * 32 + im * 16][ks * 8], LDA);
            }
#pragma unroll
            for (int jn = 0; jn < 4; jn++) {
                wmma::load_matrix_sync(bh[jn], &Bs_hi[ks * 8][wn * 64 + jn * 16], LDB);
                wmma::load_matrix_sync(bl[jn], &Bs_lo[ks * 8][wn * 64 + jn * 16], LDB);
            }
#pragma unroll
            for (int im = 0; im < 2; im++)
#pragma unroll
                for (int jn = 0; jn < 4; jn++) {
                    wmma::mma_sync(c[im][jn], ah[im], bh[jn], c[im][jn]);
                    wmma::mma_sync(c[im][jn], ah[im], bl[jn], c[im][jn]);
                    wmma::mma_sync(c[im][jn], al[im], bh[jn], c[im][jn]);
                }
        }
        __syncthreads();
    }

#pragma unroll
    for (int im = 0; im < 2; im++)
#pragma unroll
        for (int jn = 0; jn < 4; jn++)
            wmma::store_matrix_sync(
                C + (size_t)(block_row + wm * 32 + im * 16) * HDIM + wn * 64 + jn * 16,
                c[im][jn], HDIM, wmma::mem_row_major);
}

// ---------------- elementwise activations ----------------
// preprocess: h = mish(t + b_pre),  t staged in g_hg
__global__ void pre_act_kernel(const float* __restrict__ bias, int n4) {
    int i = blockIdx.x * blockDim.x + threadIdx.x;
    if (i >= n4) return;
    int c4 = i & 31;
    float4 t = reinterpret_cast<const float4*>(g_hg)[i];
    float4 b = reinterpret_cast<const float4*>(bias)[c4];
    float4 o;
    o.x = mishf(t.x + b.x);
    o.y = mishf(t.y + b.y);
    o.z = mishf(t.z + b.z);
    o.w = mishf(t.w + b.w);
    reinterpret_cast<float4*>(g_h)[i] = o;
}

// layer: h = mish(agg + skip_b + gcn_b + dis^2 * hg)   (self-loop + biases folded here)
__global__ void layer_act_kernel(const float* __restrict__ sb,
                                 const float* __restrict__ gb, int n4) {
    int i = blockIdx.x * blockDim.x + threadIdx.x;
    if (i >= n4) return;
    int row = i >> 5;
    int c4  = i & 31;
    float sl = g_dis[row]; sl *= sl;
    float4 a  = reinterpret_cast<const float4*>(g_agg)[i];
    float4 hg = reinterpret_cast<const float4*>(g_hg)[i];
    float4 b1 = reinterpret_cast<const float4*>(sb)[c4];
    float4 b2 = reinterpret_cast<const float4*>(gb)[c4];
    float4 o;
    o.x = mishf(a.x + b1.x + b2.x + sl * hg.x);
    o.y = mishf(a.y + b1.y + b2.y + sl * hg.y);
    o.z = mishf(a.z + b1.z + b2.z + sl * hg.z);
    o.w = mishf(a.w + b1.w + b2.w + sl * hg.w);
    reinterpret_cast<float4*>(g_h)[i] = o;
}

// ---------------- edge aggregation: agg[dst] += dis[src]*dis[dst]*hg[src] ----------------
#define EPW 8
__global__ __launch_bounds__(256) void edge_agg_kernel(int e) {
    int gw   = (blockIdx.x * blockDim.x + threadIdx.x) >> 5;
    int lane = threadIdx.x & 31;
    int e0 = gw * EPW;
    if (e0 >= e) return;

    int   s[EPW], d[EPW];
    float n[EPW];
    float4 v[EPW];
    bool ok[EPW];
#pragma unroll
    for (int i = 0; i < EPW; i++) {
        int ed = e0 + i;
        ok[i] = ed < e;
        if (ok[i]) {
            s[i] = g_src[ed];
            d[i] = g_dst[ed];
            n[i] = g_dis[s[i]] * g_dis[d[i]];
            v[i] = *reinterpret_cast<const float4*>(g_hg + (size_t)s[i] * HDIM + lane * 4);
        }
    }
#pragma unroll
    for (int i = 0; i < EPW; i++) {
        if (ok[i]) {
            size_t ga = __cvta_generic_to_global(g_agg + (size_t)d[i] * HDIM + lane * 4);
            asm volatile("red.global.add.v4.f32 [%0], {%1, %2, %3, %4};"
                         :: "l"(ga),
                            "f"(v[i].x * n[i]), "f"(v[i].y * n[i]),
                            "f"(v[i].z * n[i]), "f"(v[i].w * n[i])
                         : "memory");
        }
    }
}

// ---------------- post: out[i] = dot(h[i,:], W_post) + b_post ----------------
__global__ void post_kernel(const float* __restrict__ Wp,
                            const float* __restrict__ bp,
                            float* __restrict__ out, int M) {
    int warp = (blockIdx.x * blockDim.x + threadIdx.x) >> 5;
    int lane = threadIdx.x & 31;
    if (warp >= M) return;
    float4 hv = *reinterpret_cast<const float4*>(g_h + (size_t)warp * HDIM + lane * 4);
    float4 wv = *reinterpret_cast<const float4*>(Wp + lane * 4);
    float sum = hv.x * wv.x + hv.y * wv.y + hv.z * wv.z + hv.w * wv.w;
#pragma unroll
    for (int o = 16; o > 0; o >>= 1) sum += __shfl_xor_sync(0xFFFFFFFFu, sum, o);
    if (lane == 0) out[warp] = sum + bp[0];
}

// ---------------- launch ----------------
extern "C" void kernel_launch(void* const* d_in, const int* in_sizes, int n_in,
                              void* d_out, int out_size) {
    const float* x      = (const float*)d_in[0];
    const int*   ei     = (const int*)d_in[1];     // int32 (JAX x64-disabled)
    const float* W_pre  = (const float*)d_in[2];
    const float* b_pre  = (const float*)d_in[3];
    const float* gcn_W  = (const float*)d_in[4];
    const float* gcn_b  = (const float*)d_in[5];
    const float* skip_W = (const float*)d_in[6];
    const float* skip_b = (const float*)d_in[7];
    const float* W_post = (const float*)d_in[8];
    const float* b_post = (const float*)d_in[9];
    float*       out    = (float*)d_out;

    const int M = in_sizes[0] / HDIM;          // 50000
    const int E = in_sizes[1] / 2;             // 1600000
    const int L = in_sizes[4] / (HDIM * HDIM); // 3
    const int n4 = NPAD * (HDIM / 4);          // float4 count incl. padding

    // device pointers to scratch (resolved at compile time inside kernels)
    float* d_h   = nullptr;   // unused host-side; kernels reference globals directly
    (void)d_h;

    const int TB = 256;
    const int gemm_blocks = NPAD / 128;                    // 392
    const int node_blocks = (NPAD + TB - 1) / TB;
    const int edge_blocks = (E + TB - 1) / TB;
    const int n4_blocks   = (n4 + TB - 1) / TB;
    const int agg_warps   = (E + EPW - 1) / EPW;
    const int agg_blocks  = (agg_warps * 32 + TB - 1) / TB;
    const int post_blocks = (M * 32 + TB - 1) / TB;

    // Degrees + normalization (padded rows get deg=1 -> dis=1, harmless)
    init_deg_kernel<<<node_blocks, TB>>>(NPAD);
    build_edges_kernel<<<edge_blocks, TB>>>(ei, E, M);
    dis_kernel<<<node_blocks, TB>>>(NPAD);

    // need global-symbol addresses for GEMM A/C args
    // (kernels take raw pointers; use the device globals via unqualified device symbols)
    // We get them by launching with pointers obtained from the symbols at compile time:
    // simplest portable way: small helper kernels already reference globals; for GEMM we
    // pass addresses via separate launches below using the symbol-decay trick.

    // Preprocess: t = x @ W_pre (raw) -> g_hg ; h = mish(t + b_pre)
    {
        // device-symbol addresses are valid to take in host code only via cudaGetSymbolAddress,
        // which is capture-safe NOT guaranteed; instead each GEMM variant binds C internally.
        // We pass nullptr and select buffers by an int tag... (see wrapper below)
    }

    // --- GEMM wrapper kernels bind the global buffers without host symbol lookup ---
    // (implemented as separate launches through a tag parameter)
    extern __global__ void tf32_gemm_kernel(const float*, const float*, float*, int);

    // helper lambdas using tag-dispatch kernels defined below
    // (definitions after this function would not be visible; so we use the tag kernel)
    void run_gemm_tag(int, const float*, const float*, int, int);
    (void)run_gemm_tag;

    // NOTE: actual dispatch below via g_gemm_tag kernel
    // Preprocess
    {
        // t = x @ W_pre -> g_hg
        extern __global__ void gemm_tag_kernel(int tag, const float* Aext, const float* B, int Mload);
        gemm_tag_kernel<<<gemm_blocks, TB>>>(0, x, W_pre, M);
        pre_act_kernel<<<n4_blocks, TB>>>(b_pre, n4);
    }

    for (int l = 0; l < L; l++) {
        const float* gW = gcn_W  + (size_t)l * HDIM * HDIM;
        const float* sW = skip_W + (size_t)l * HDIM * HDIM;
        const float* gb = gcn_b  + (size_t)l * HDIM;
        const float* sb = skip_b + (size_t)l * HDIM;

        extern __global__ void gemm_tag_kernel(int tag, const float* Aext, const float* B, int Mload);
        gemm_tag_kernel<<<gemm_blocks, TB>>>(1, nullptr, gW, NPAD);  // g_hg  = h @ gcn_W
        gemm_tag_kernel<<<gemm_blocks, TB>>>(2, nullptr, sW, NPAD);  // g_agg = h @ skip_W
        edge_agg_kernel<<<agg_blocks, TB>>>(E);
        layer_act_kernel<<<n4_blocks, TB>>>(sb, gb, n4);
    }

    post_kernel<<<post_blocks, TB>>>(W_post, b_post, out, M);
}

// ---------------- tag-dispatch GEMM (binds device globals without symbol lookup) ----------------
// tag 0: A = ext(x),  C = g_hg
// tag 1: A = g_h,     C = g_hg
// tag 2: A = g_h,     C = g_agg
__global__ __launch_bounds__(256) void gemm_tag_kernel(
    int tag, const float* __restrict__ Aext, const float* __restrict__ B, int Mload)
{
    __shared__ float As_hi[128][LDA];
    __shared__ float As_lo[128][LDA];
    __shared__ float Bs_hi[KC][LDB];
    __shared__ float Bs_lo[KC][LDB];

    const float* __restrict__ A = (tag == 0) ? Aext : g_h;
    float* __restrict__ C = (tag == 2) ? g_agg : g_hg;

    int tid  = threadIdx.x;
    int warp = tid >> 5;
    int wm   = warp >> 1;
    int wn   = warp & 1;
    int block_row = blockIdx.x * 128;

    wmma::fragment<wmma::accumulator, 16, 16, 8, float> c[2][4];
#pragma unroll
    for (int im = 0; im < 2; im++)
#pragma unroll
        for (int jn = 0; jn < 4; jn++) wmma::fill_fragment(c[im][jn], 0.0f);

    for (int k0 = 0; k0 < HDIM; k0 += KC) {
#pragma unroll
        for (int it = 0; it < 2; it++) {
            int idx = tid + it * 256;
            int r   = idx >> 2;
            int c4  = (idx & 3) << 2;
            float4 a = make_float4(0.f, 0.f, 0.f, 0.f);
            if (block_row + r < Mload)
                a = *reinterpret_cast<const float4*>(A + (size_t)(block_row + r) * HDIM + k0 + c4);
            float h0 = to_tf32(a.x), h1 = to_tf32(a.y), h2 = to_tf32(a.z), h3 = to_tf32(a.w);
            As_hi[r][c4 + 0] = h0;  As_lo[r][c4 + 0] = to_tf32(a.x - h0);
            As_hi[r][c4 + 1] = h1;  As_lo[r][c4 + 1] = to_tf32(a.y - h1);
            As_hi[r][c4 + 2] = h2;  As_lo[r][c4 + 2] = to_tf32(a.z - h2);
            As_hi[r][c4 + 3] = h3;  As_lo[r][c4 + 3] = to_tf32(a.w - h3);
        }
#pragma unroll
        for (int it = 0; it < 2; it++) {
            int idx = tid + it * 256;
            int r   = idx >> 5;
            int cc  = (idx & 31) << 2;
            float4 b = *reinterpret_cast<const float4*>(B + (size_t)(k0 + r) * HDIM + cc);
            float h0 = to_tf32(b.x), h1 = to_tf32(b.y), h2 = to_tf32(b.z), h3 = to_tf32(b.w);
            Bs_hi[r][cc + 0] = h0;  Bs_lo[r][cc + 0] = to_tf32(b.x - h0);
            Bs_hi[r][cc + 1] = h1;  Bs_lo[r][cc + 1] = to_tf32(b.y - h1);
            Bs_hi[r][cc + 2] = h2;  Bs_lo[r][cc + 2] = to_tf32(b.z - h2);
            Bs_hi[r][cc + 3] = h3;  Bs_lo[r][cc + 3] = to_tf32(b.w - h3);
        }
        __syncthreads();

#pragma unroll
        for (int ks = 0; ks < KC / 8; ks++) {
            wmma::fragment<wmma::matrix_a, 16, 16, 8, wmma::precision::tf32, wmma::row_major> ah[2], al[2];
            wmma::fragment<wmma::matrix_b, 16, 16, 8, wmma::precision::tf32, wmma::row_major> bh[4], bl[4];
#pragma unroll
            for (int im = 0; im < 2; im++) {
                wmma::load_matrix_sync(ah[im], &As_hi[wm * 32 + im * 16][ks * 8], LDA);
                wmma::load_matrix_sync(al[im], &As_lo[wm * 32 + im * 16][ks * 8], LDA);
            }
#pragma unroll
            for (int jn = 0; jn < 4; jn++) {
                wmma::load_matrix_sync(bh[jn], &Bs_hi[ks * 8][wn * 64 + jn * 16], LDB);
                wmma::load_matrix_sync(bl[jn], &Bs_lo[ks * 8][wn * 64 + jn * 16], LDB);
            }
#pragma unroll
            for (int im = 0; im < 2; im++)
#pragma unroll
                for (int jn = 0; jn < 4; jn++) {
                    wmma::mma_sync(c[im][jn], ah[im], bh[jn], c[im][jn]);
                    wmma::mma_sync(c[im][jn], ah[im], bl[jn], c[im][jn]);
                    wmma::mma_sync(c[im][jn], al[im], bh[jn], c[im][jn]);
                }
        }
        __syncthreads();
    }

#pragma unroll
    for (int im = 0; im < 2; im++)
#pragma unroll
        for (int jn = 0; jn < 4; jn++)
            wmma::store_matrix_sync(
                C + (size_t)(block_row + wm * 32 + im * 16) * HDIM + wn * 64 + jn * 16,
                c[im][jn], HDIM, wmma::mem_row_major);
}

// round 6
// speedup vs baseline: 1.0481x; 1.0481x over previous
#include <cuda_runtime.h>
#include <math.h>
#include <mma.h>

using namespace nvcuda;

// Problem constants
#define NN    50000
#define NPAD  50176            // 392 * 128: full tiles, no bounds checks in GEMM
#define EE    1600000
#define HDIM  128
#define NMAT  7                // W_pre + 3 gcn + 3 skip

// ---------------- static device scratch (allocation-free) ----------------
__device__ __align__(16) int   g_src[EE];
__device__ __align__(16) int   g_dst[EE];
__device__ __align__(16) float g_deg[NPAD];
__device__ __align__(16) float g_dis[NPAD];
__device__ __align__(16) float g_ahi[(size_t)NPAD * HDIM];  // A operand, tf32-hi
__device__ __align__(16) float g_alo[(size_t)NPAD * HDIM];  // A operand, tf32-lo
__device__ __align__(16) float g_hg [(size_t)NPAD * HDIM];
__device__ __align__(16) float g_agg[(size_t)NPAD * HDIM];
__device__ __align__(16) float g_bhi[(size_t)NMAT * HDIM * HDIM];
__device__ __align__(16) float g_blo[(size_t)NMAT * HDIM * HDIM];

// ---------------- math helpers ----------------
__device__ __forceinline__ float mishf(float x) {
    float sp = fmaxf(x, 0.0f) + log1pf(expf(-fabsf(x)));
    return x * tanhf(sp);
}
__device__ __forceinline__ float to_tf32(float x) {
    unsigned r;
    asm("cvt.rna.tf32.f32 %0, %1;" : "=r"(r) : "f"(x));
    return __uint_as_float(r);
}
__device__ __forceinline__ void split4(float4 v, float4& hi, float4& lo) {
    hi.x = to_tf32(v.x); lo.x = to_tf32(v.x - hi.x);
    hi.y = to_tf32(v.y); lo.y = to_tf32(v.y - hi.y);
    hi.z = to_tf32(v.z); lo.z = to_tf32(v.z - hi.z);
    hi.w = to_tf32(v.w); lo.w = to_tf32(v.w - hi.w);
}
__device__ __forceinline__ void cp_async16(void* smem_dst, const void* gmem_src) {
    unsigned s = (unsigned)__cvta_generic_to_shared(smem_dst);
    asm volatile("cp.async.ca.shared.global [%0], [%1], 16;" :: "r"(s), "l"(gmem_src) : "memory");
}

// ---------------- small kernels ----------------
__global__ void init_deg_kernel(int n) {
    int i = blockIdx.x * blockDim.x + threadIdx.x;
    if (i < n) g_deg[i] = 1.0f;
}
__global__ void build_edges_kernel(const int* __restrict__ ei, int e, int n) {
    int i = blockIdx.x * blockDim.x + threadIdx.x;
    if (i < e) {
        int s = ei[i];
        int d = ei[e + i];
        if ((unsigned)s >= (unsigned)n) s = 0;
        if ((unsigned)d >= (unsigned)n) d = 0;
        g_src[i] = s;
        g_dst[i] = d;
        atomicAdd(&g_deg[d], 1.0f);
    }
}
__global__ void dis_kernel(int n) {
    int i = blockIdx.x * blockDim.x + threadIdx.x;
    if (i < n) g_dis[i] = rsqrtf(g_deg[i]);
}

// split external x (M real rows, pad -> 0) into g_ahi/g_alo
__global__ void split_x_kernel(const float* __restrict__ x, int M, int n4) {
    int i = blockIdx.x * blockDim.x + threadIdx.x;
    if (i >= n4) return;
    int row = i >> 5;
    float4 v = make_float4(0.f, 0.f, 0.f, 0.f);
    if (row < M) v = reinterpret_cast<const float4*>(x)[i];
    float4 hi, lo; split4(v, hi, lo);
    reinterpret_cast<float4*>(g_ahi)[i] = hi;
    reinterpret_cast<float4*>(g_alo)[i] = lo;
}

// split one 128x128 weight matrix into slot 'off4' (float4 units) of g_bhi/g_blo
__global__ void split_w_kernel(const float* __restrict__ W, int off4) {
    int i = blockIdx.x * blockDim.x + threadIdx.x;
    if (i >= HDIM * HDIM / 4) return;
    float4 v = reinterpret_cast<const float4*>(W)[i];
    float4 hi, lo; split4(v, hi, lo);
    reinterpret_cast<float4*>(g_bhi)[off4 + i] = hi;
    reinterpret_cast<float4*>(g_blo)[off4 + i] = lo;
}

// ---------------- 3xTF32 GEMM on pre-split operands ----------------
// C[NPAD,128] = (Ahi+Alo) @ (Bhi+Blo), D += Ahi*Bhi + Ahi*Blo + Alo*Bhi
// ctag 0: C = g_hg ; ctag 1: C = g_agg.  B slot = bsel.
#define KC  16
#define LDA 20
#define LDB 132

__global__ __launch_bounds__(256, 2) void gemm_ts_kernel(int ctag, int bsel) {
    __shared__ float As_hi[128][LDA];
    __shared__ float As_lo[128][LDA];
    __shared__ float Bs_hi[KC][LDB];
    __shared__ float Bs_lo[KC][LDB];

    float* __restrict__ C = ctag ? g_agg : g_hg;
    const float* __restrict__ Bhi = g_bhi + (size_t)bsel * HDIM * HDIM;
    const float* __restrict__ Blo = g_blo + (size_t)bsel * HDIM * HDIM;

    int tid  = threadIdx.x;
    int warp = tid >> 5;
    int wm   = warp >> 1;            // 0..3 -> 32-row band
    int wn   = warp & 1;             // 0..1 -> 64-col band
    int block_row = blockIdx.x * 128;

    wmma::fragment<wmma::accumulator, 16, 16, 8, float> c[2][4];
#pragma unroll
    for (int im = 0; im < 2; im++)
#pragma unroll
        for (int jn = 0; jn < 4; jn++) wmma::fill_fragment(c[im][jn], 0.0f);

    for (int k0 = 0; k0 < HDIM; k0 += KC) {
        // A tiles: 128 x KC hi+lo, pure async copies
#pragma unroll
        for (int it = 0; it < 2; it++) {
            int idx = tid + it * 256;            // 0..511
            int r   = idx >> 2;
            int c4  = (idx & 3) << 2;
            size_t go = (size_t)(block_row + r) * HDIM + k0 + c4;
            cp_async16(&As_hi[r][c4], g_ahi + go);
            cp_async16(&As_lo[r][c4], g_alo + go);
        }
        // B tiles: KC x 128 hi+lo
#pragma unroll
        for (int it = 0; it < 2; it++) {
            int idx = tid + it * 256;
            int r   = idx >> 5;
            int cc  = (idx & 31) << 2;
            size_t go = (size_t)(k0 + r) * HDIM + cc;
            cp_async16(&Bs_hi[r][cc], Bhi + go);
            cp_async16(&Bs_lo[r][cc], Blo + go);
        }
        asm volatile("cp.async.commit_group;" ::: "memory");
        asm volatile("cp.async.wait_group 0;" ::: "memory");
        __syncthreads();

#pragma unroll
        for (int ks = 0; ks < KC / 8; ks++) {
            wmma::fragment<wmma::matrix_a, 16, 16, 8, wmma::precision::tf32, wmma::row_major> ah[2], al[2];
            wmma::fragment<wmma::matrix_b, 16, 16, 8, wmma::precision::tf32, wmma::row_major> bh[4], bl[4];
#pragma unroll
            for (int im = 0; im < 2; im++) {
                wmma::load_matrix_sync(ah[im], &As_hi[wm * 32 + im * 16][ks * 8], LDA);
                wmma::load_matrix_sync(al[im], &As_lo[wm * 32 + im * 16][ks * 8], LDA);
            }
#pragma unroll
            for (int jn = 0; jn < 4; jn++) {
                wmma::load_matrix_sync(bh[jn], &Bs_hi[ks * 8][wn * 64 + jn * 16], LDB);
                wmma::load_matrix_sync(bl[jn], &Bs_lo[ks * 8][wn * 64 + jn * 16], LDB);
            }
#pragma unroll
            for (int im = 0; im < 2; im++)
#pragma unroll
                for (int jn = 0; jn < 4; jn++) {
                    wmma::mma_sync(c[im][jn], ah[im], bh[jn], c[im][jn]);
                    wmma::mma_sync(c[im][jn], ah[im], bl[jn], c[im][jn]);
                    wmma::mma_sync(c[im][jn], al[im], bh[jn], c[im][jn]);
                }
        }
        __syncthreads();
    }

#pragma unroll
    for (int im = 0; im < 2; im++)
#pragma unroll
        for (int jn = 0; jn < 4; jn++)
            wmma::store_matrix_sync(
                C + (size_t)(block_row + wm * 32 + im * 16) * HDIM + wn * 64 + jn * 16,
                c[im][jn], HDIM, wmma::mem_row_major);
}

// ---------------- activations (produce pre-split next-layer A) ----------------
// preprocess: h = mish(t + b_pre), t = g_hg; write split h
__global__ void pre_act_kernel(const float* __restrict__ bias, int n4) {
    int i = blockIdx.x * blockDim.x + threadIdx.x;
    if (i >= n4) return;
    int c4 = i & 31;
    float4 t = reinterpret_cast<const float4*>(g_hg)[i];
    float4 b = reinterpret_cast<const float4*>(bias)[c4];
    float4 o;
    o.x = mishf(t.x + b.x);
    o.y = mishf(t.y + b.y);
    o.z = mishf(t.z + b.z);
    o.w = mishf(t.w + b.w);
    float4 hi, lo; split4(o, hi, lo);
    reinterpret_cast<float4*>(g_ahi)[i] = hi;
    reinterpret_cast<float4*>(g_alo)[i] = lo;
}

// layer: h = mish(agg + skip_b + gcn_b + dis^2 * hg); write split h
__global__ void layer_act_kernel(const float* __restrict__ sb,
                                 const float* __restrict__ gb, int n4) {
    int i = blockIdx.x * blockDim.x + threadIdx.x;
    if (i >= n4) return;
    int row = i >> 5;
    int c4  = i & 31;
    float sl = g_dis[row]; sl *= sl;
    float4 a  = reinterpret_cast<const float4*>(g_agg)[i];
    float4 hg = reinterpret_cast<const float4*>(g_hg)[i];
    float4 b1 = reinterpret_cast<const float4*>(sb)[c4];
    float4 b2 = reinterpret_cast<const float4*>(gb)[c4];
    float4 o;
    o.x = mishf(a.x + b1.x + b2.x + sl * hg.x);
    o.y = mishf(a.y + b1.y + b2.y + sl * hg.y);
    o.z = mishf(a.z + b1.z + b2.z + sl * hg.z);
    o.w = mishf(a.w + b1.w + b2.w + sl * hg.w);
    float4 hi, lo; split4(o, hi, lo);
    reinterpret_cast<float4*>(g_ahi)[i] = hi;
    reinterpret_cast<float4*>(g_alo)[i] = lo;
}

// ---------------- edge aggregation: agg[dst] += dis[src]*dis[dst]*hg[src] ----------------
#define EPW 8
__global__ __launch_bounds__(256) void edge_agg_kernel(int e) {
    int gw   = (blockIdx.x * blockDim.x + threadIdx.x) >> 5;
    int lane = threadIdx.x & 31;
    int e0 = gw * EPW;
    if (e0 >= e) return;

    int   s[EPW], d[EPW];
    float n[EPW];
    float4 v[EPW];
    bool ok[EPW];
#pragma unroll
    for (int i = 0; i < EPW; i++) {
        int ed = e0 + i;
        ok[i] = ed < e;
        if (ok[i]) {
            s[i] = g_src[ed];
            d[i] = g_dst[ed];
            n[i] = g_dis[s[i]] * g_dis[d[i]];
            v[i] = *reinterpret_cast<const float4*>(g_hg + (size_t)s[i] * HDIM + lane * 4);
        }
    }
#pragma unroll
    for (int i = 0; i < EPW; i++) {
        if (ok[i]) {
            size_t ga = __cvta_generic_to_global(g_agg + (size_t)d[i] * HDIM + lane * 4);
            asm volatile("red.global.add.v4.f32 [%0], {%1, %2, %3, %4};"
                         :: "l"(ga),
                            "f"(v[i].x * n[i]), "f"(v[i].y * n[i]),
                            "f"(v[i].z * n[i]), "f"(v[i].w * n[i])
                         : "memory");
        }
    }
}

// ---------------- post: out[i] = dot(h[i,:], W_post) + b_post, h = ahi+alo ----------------
__global__ void post_kernel(const float* __restrict__ Wp,
                            const float* __restrict__ bp,
                            float* __restrict__ out, int M) {
    int warp = (blockIdx.x * blockDim.x + threadIdx.x) >> 5;
    int lane = threadIdx.x & 31;
    if (warp >= M) return;
    float4 hh = *reinterpret_cast<const float4*>(g_ahi + (size_t)warp * HDIM + lane * 4);
    float4 hl = *reinterpret_cast<const float4*>(g_alo + (size_t)warp * HDIM + lane * 4);
    float4 wv = *reinterpret_cast<const float4*>(Wp + lane * 4);
    float sum = (hh.x + hl.x) * wv.x + (hh.y + hl.y) * wv.y
              + (hh.z + hl.z) * wv.z + (hh.w + hl.w) * wv.w;
#pragma unroll
    for (int o = 16; o > 0; o >>= 1) sum += __shfl_xor_sync(0xFFFFFFFFu, sum, o);
    if (lane == 0) out[warp] = sum + bp[0];
}

// ---------------- launch ----------------
extern "C" void kernel_launch(void* const* d_in, const int* in_sizes, int n_in,
                              void* d_out, int out_size) {
    const float* x      = (const float*)d_in[0];
    const int*   ei     = (const int*)d_in[1];     // int32 (JAX x64-disabled)
    const float* W_pre  = (const float*)d_in[2];
    const float* b_pre  = (const float*)d_in[3];
    const float* gcn_W  = (const float*)d_in[4];
    const float* gcn_b  = (const float*)d_in[5];
    const float* skip_W = (const float*)d_in[6];
    const float* skip_b = (const float*)d_in[7];
    const float* W_post = (const float*)d_in[8];
    const float* b_post = (const float*)d_in[9];
    float*       out    = (float*)d_out;

    const int M = in_sizes[0] / HDIM;          // 50000
    const int E = in_sizes[1] / 2;             // 1600000
    const int L = in_sizes[4] / (HDIM * HDIM); // 3
    const int n4 = NPAD * (HDIM / 4);

    const int TB = 256;
    const int gemm_blocks = NPAD / 128;                    // 392
    const int node_blocks = (NPAD + TB - 1) / TB;
    const int edge_blocks = (E + TB - 1) / TB;
    const int n4_blocks   = (n4 + TB - 1) / TB;
    const int w4_blocks   = (HDIM * HDIM / 4 + TB - 1) / TB;
    const int agg_warps   = (E + EPW - 1) / EPW;
    const int agg_blocks  = (agg_warps * 32 + TB - 1) / TB;
    const int post_blocks = (M * 32 + TB - 1) / TB;

    // Degrees + normalization (pad rows deg=1 -> dis=1, harmless)
    init_deg_kernel<<<node_blocks, TB>>>(NPAD);
    build_edges_kernel<<<edge_blocks, TB>>>(ei, E, M);
    dis_kernel<<<node_blocks, TB>>>(NPAD);

    // Pre-split all weight matrices into tf32 hi/lo slots
    const int W4 = HDIM * HDIM / 4;
    split_w_kernel<<<w4_blocks, TB>>>(W_pre, 0 * W4);
    for (int l = 0; l < L; l++) {
        split_w_kernel<<<w4_blocks, TB>>>(gcn_W  + (size_t)l * HDIM * HDIM, (1 + l) * W4);
        split_w_kernel<<<w4_blocks, TB>>>(skip_W + (size_t)l * HDIM * HDIM, (4 + l) * W4);
    }

    // Preprocess: split x, t = x @ W_pre -> g_hg, h = mish(t + b_pre) (split)
    split_x_kernel<<<n4_blocks, TB>>>(x, M, n4);
    gemm_ts_kernel<<<gemm_blocks, TB>>>(0, 0);
    pre_act_kernel<<<n4_blocks, TB>>>(b_pre, n4);

    for (int l = 0; l < L; l++) {
        const float* gb = gcn_b  + (size_t)l * HDIM;
        const float* sb = skip_b + (size_t)l * HDIM;

        gemm_ts_kernel<<<gemm_blocks, TB>>>(0, 1 + l);   // g_hg  = h @ gcn_W
        gemm_ts_kernel<<<gemm_blocks, TB>>>(1, 4 + l);   // g_agg = h @ skip_W
        edge_agg_kernel<<<agg_blocks, TB>>>(E);          // agg += messages
        layer_act_kernel<<<n4_blocks, TB>>>(sb, gb, n4); // h = mish(...), split
    }

    post_kernel<<<post_blocks, TB>>>(W_post, b_post, out, M);
}

// round 7
// speedup vs baseline: 1.2649x; 1.2068x over previous
#include <cuda_runtime.h>
#include <math.h>

// Problem constants
#define NN    50000
#define NPAD  50176            // 392 * 128: full GEMM tiles, no store guards
#define EE    1600000
#define HDIM  128

// ---------------- static device scratch (allocation-free) ----------------
__device__ __align__(16) int   g_src[EE];
__device__ __align__(16) int   g_dst[EE];
__device__ __align__(16) float g_deg[NPAD];
__device__ __align__(16) float g_dis[NPAD];
__device__ __align__(16) float g_h  [(size_t)NPAD * HDIM];
__device__ __align__(16) float g_hg [(size_t)NPAD * HDIM];
__device__ __align__(16) float g_agg[(size_t)NPAD * HDIM];

// ---------------- math helpers ----------------
__device__ __forceinline__ float mishf(float x) {
    float sp = fmaxf(x, 0.0f) + log1pf(expf(-fabsf(x)));
    return x * tanhf(sp);
}
__device__ __forceinline__ void cp_async16(void* smem_dst, const void* gmem_src) {
    unsigned s = (unsigned)__cvta_generic_to_shared(smem_dst);
    asm volatile("cp.async.ca.shared.global [%0], [%1], 16;" :: "r"(s), "l"(gmem_src) : "memory");
}

// ---------------- small kernels ----------------
__global__ void init_deg_kernel(int n) {
    int i = blockIdx.x * blockDim.x + threadIdx.x;
    if (i < n) g_deg[i] = 1.0f;   // self-loop; pad rows harmlessly 1
}
__global__ void build_edges_kernel(const int* __restrict__ ei, int e, int n) {
    int i = blockIdx.x * blockDim.x + threadIdx.x;
    if (i < e) {
        int s = ei[i];
        int d = ei[e + i];
        if ((unsigned)s >= (unsigned)n) s = 0;
        if ((unsigned)d >= (unsigned)n) d = 0;
        g_src[i] = s;
        g_dst[i] = d;
        atomicAdd(&g_deg[d], 1.0f);
    }
}
__global__ void dis_kernel(int n) {
    int i = blockIdx.x * blockDim.x + threadIdx.x;
    if (i < n) g_dis[i] = rsqrtf(g_deg[i]);
}

// ---------------- SGEMM: NPAD x 128 x 128, row-major A and B ----------------
// MODE 0: A = x (guarded), C = g_h,   C = mish(acc + bias)            (preprocess)
// MODE 1: A = g_h,         C = g_hg,  C = acc                         (gcn branch)
// MODE 3: A = g_h,         C = g_agg, C = acc + bias + bias2 + dis^2*hg  (skip + agg init)
#define KC 32
template <int MODE>
__global__ __launch_bounds__(256, 2) void sgemm128_kernel(
    const float* __restrict__ Aext,
    const float* __restrict__ B,
    const float* __restrict__ bias,
    const float* __restrict__ bias2,
    int M)
{
    const int K = 128, Ncols = 128;
    __shared__ float As[KC][128];    // transposed: As[k][m]
    __shared__ float Bs[KC][132];    // Bs[k][n], padded

    const float* __restrict__ A = (MODE == 0) ? Aext : g_h;
    float* __restrict__ C = (MODE == 0) ? g_h : (MODE == 1 ? g_hg : g_agg);

    int tid = threadIdx.x;
    int block_row = blockIdx.x * 128;
    int tx = tid & 15;   // col group (8 cols)
    int ty = tid >> 4;   // row group (8 rows)

    float acc[8][8];
#pragma unroll
    for (int i = 0; i < 8; i++)
#pragma unroll
        for (int j = 0; j < 8; j++) acc[i][j] = 0.0f;

    for (int k0 = 0; k0 < K; k0 += KC) {
        // B tile: KC x 128 via cp.async (no register staging)
#pragma unroll
        for (int it = 0; it < 4; it++) {
            int idx = tid + it * 256;            // 0..1023 float4 slots
            int r   = idx >> 5;                  // 0..31
            int cc  = (idx & 31) << 2;           // 0..124
            cp_async16(&Bs[r][cc], B + (size_t)(k0 + r) * Ncols + cc);
        }
        // A tile: 128 x KC, register-staged transpose
#pragma unroll
        for (int it = 0; it < 4; it++) {
            int idx = tid + it * 256;            // 0..1023
            int r   = idx >> 3;                  // 0..127
            int c4  = (idx & 7) << 2;            // 0,4,...,28
            float4 a;
            if (MODE == 0) {
                a = make_float4(0.f, 0.f, 0.f, 0.f);
                if (block_row + r < M)
                    a = *reinterpret_cast<const float4*>(A + (size_t)(block_row + r) * K + k0 + c4);
            } else {
                a = *reinterpret_cast<const float4*>(A + (size_t)(block_row + r) * K + k0 + c4);
            }
            As[c4 + 0][r] = a.x;
            As[c4 + 1][r] = a.y;
            As[c4 + 2][r] = a.z;
            As[c4 + 3][r] = a.w;
        }
        asm volatile("cp.async.commit_group;" ::: "memory");
        asm volatile("cp.async.wait_group 0;" ::: "memory");
        __syncthreads();

#pragma unroll
        for (int kk = 0; kk < KC; kk++) {
            float ra[8], rb[8];
            *reinterpret_cast<float4*>(ra)     = *reinterpret_cast<const float4*>(&As[kk][ty * 8]);
            *reinterpret_cast<float4*>(ra + 4) = *reinterpret_cast<const float4*>(&As[kk][ty * 8 + 4]);
            *reinterpret_cast<float4*>(rb)     = *reinterpret_cast<const float4*>(&Bs[kk][tx * 8]);
            *reinterpret_cast<float4*>(rb + 4) = *reinterpret_cast<const float4*>(&Bs[kk][tx * 8 + 4]);
#pragma unroll
            for (int i = 0; i < 8; i++)
#pragma unroll
                for (int j = 0; j < 8; j++)
                    acc[i][j] = fmaf(ra[i], rb[j], acc[i][j]);
        }
        __syncthreads();
    }

    // Epilogue (stores always in-bounds thanks to NPAD)
#pragma unroll
    for (int i = 0; i < 8; i++) {
        int gr = block_row + ty * 8 + i;
        float* crow = C + (size_t)gr * Ncols + tx * 8;
        float sl = 0.0f;
        float hgv[8];
        if (MODE == 3) {
            sl = g_dis[gr]; sl *= sl;
            const float* hr = g_hg + (size_t)gr * Ncols + tx * 8;
            *reinterpret_cast<float4*>(hgv)     = *reinterpret_cast<const float4*>(hr);
            *reinterpret_cast<float4*>(hgv + 4) = *reinterpret_cast<const float4*>(hr + 4);
        }
#pragma unroll
        for (int j = 0; j < 8; j++) {
            float v = acc[i][j];
            if (MODE == 0) { v += bias[tx * 8 + j]; v = mishf(v); }
            else if (MODE == 3) { v += bias[tx * 8 + j] + bias2[tx * 8 + j] + sl * hgv[j]; }
            crow[j] = v;
        }
    }
}

// ---------------- edge aggregation: agg[dst] += dis[src]*dis[dst]*hg[src] ----------------
#define EPW 8
__global__ __launch_bounds__(256) void edge_agg_kernel(int e) {
    int gw   = (blockIdx.x * blockDim.x + threadIdx.x) >> 5;
    int lane = threadIdx.x & 31;
    int e0 = gw * EPW;
    if (e0 >= e) return;

    int   s[EPW], d[EPW];
    float n[EPW];
    float4 v[EPW];
    bool ok[EPW];
#pragma unroll
    for (int i = 0; i < EPW; i++) {
        int ed = e0 + i;
        ok[i] = ed < e;
        if (ok[i]) {
            s[i] = g_src[ed];
            d[i] = g_dst[ed];
            n[i] = g_dis[s[i]] * g_dis[d[i]];
            v[i] = *reinterpret_cast<const float4*>(g_hg + (size_t)s[i] * HDIM + lane * 4);
        }
    }
#pragma unroll
    for (int i = 0; i < EPW; i++) {
        if (ok[i]) {
            size_t ga = __cvta_generic_to_global(g_agg + (size_t)d[i] * HDIM + lane * 4);
            asm volatile("red.global.add.v4.f32 [%0], {%1, %2, %3, %4};"
                         :: "l"(ga),
                            "f"(v[i].x * n[i]), "f"(v[i].y * n[i]),
                            "f"(v[i].z * n[i]), "f"(v[i].w * n[i])
                         : "memory");
        }
    }
}

// ---------------- layer epilogue: h = mish(agg) ----------------
__global__ void mish_kernel(int n4) {
    int i = blockIdx.x * blockDim.x + threadIdx.x;
    if (i >= n4) return;
    float4 a = reinterpret_cast<const float4*>(g_agg)[i];
    float4 o;
    o.x = mishf(a.x);
    o.y = mishf(a.y);
    o.z = mishf(a.z);
    o.w = mishf(a.w);
    reinterpret_cast<float4*>(g_h)[i] = o;
}

// ---------------- post: out[i] = dot(h[i,:], W_post) + b_post ----------------
__global__ void post_kernel(const float* __restrict__ Wp,
                            const float* __restrict__ bp,
                            float* __restrict__ out, int M) {
    int warp = (blockIdx.x * blockDim.x + threadIdx.x) >> 5;
    int lane = threadIdx.x & 31;
    if (warp >= M) return;
    float4 hv = *reinterpret_cast<const float4*>(g_h + (size_t)warp * HDIM + lane * 4);
    float4 wv = *reinterpret_cast<const float4*>(Wp + lane * 4);
    float sum = hv.x * wv.x + hv.y * wv.y + hv.z * wv.z + hv.w * wv.w;
#pragma unroll
    for (int o = 16; o > 0; o >>= 1) sum += __shfl_xor_sync(0xFFFFFFFFu, sum, o);
    if (lane == 0) out[warp] = sum + bp[0];
}

// ---------------- launch ----------------
extern "C" void kernel_launch(void* const* d_in, const int* in_sizes, int n_in,
                              void* d_out, int out_size) {
    const float* x      = (const float*)d_in[0];
    const int*   ei     = (const int*)d_in[1];     // int32 (JAX x64-disabled)
    const float* W_pre  = (const float*)d_in[2];
    const float* b_pre  = (const float*)d_in[3];
    const float* gcn_W  = (const float*)d_in[4];
    const float* gcn_b  = (const float*)d_in[5];
    const float* skip_W = (const float*)d_in[6];
    const float* skip_b = (const float*)d_in[7];
    const float* W_post = (const float*)d_in[8];
    const float* b_post = (const float*)d_in[9];
    float*       out    = (float*)d_out;

    const int M = in_sizes[0] / HDIM;          // 50000
    const int E = in_sizes[1] / 2;             // 1600000
    const int L = in_sizes[4] / (HDIM * HDIM); // 3
    const int n4 = NPAD * (HDIM / 4);

    const int TB = 256;
    const int gemm_blocks = NPAD / 128;        // 392
    const int node_blocks = (NPAD + TB - 1) / TB;
    const int edge_blocks = (E + TB - 1) / TB;
    const int n4_blocks   = (n4 + TB - 1) / TB;
    const int agg_warps   = (E + EPW - 1) / EPW;
    const int agg_blocks  = (agg_warps * 32 + TB - 1) / TB;
    const int post_blocks = (M * 32 + TB - 1) / TB;

    // Degrees + normalization (pad rows: deg=1 -> dis=1, harmless)
    init_deg_kernel<<<node_blocks, TB>>>(NPAD);
    build_edges_kernel<<<edge_blocks, TB>>>(ei, E, M);
    dis_kernel<<<node_blocks, TB>>>(NPAD);

    // Preprocess: h = mish(x @ W_pre + b_pre)
    sgemm128_kernel<0><<<gemm_blocks, TB>>>(x, W_pre, b_pre, nullptr, M);

    // GCN layers
    for (int l = 0; l < L; l++) {
        const float* gW = gcn_W  + (size_t)l * HDIM * HDIM;
        const float* sW = skip_W + (size_t)l * HDIM * HDIM;
        const float* gb = gcn_b  + (size_t)l * HDIM;
        const float* sb = skip_b + (size_t)l * HDIM;

        // hg = h @ gcn_W
        sgemm128_kernel<1><<<gemm_blocks, TB>>>(nullptr, gW, nullptr, nullptr, M);
        // agg = h @ skip_W + skip_b + gcn_b + dis^2*hg
        sgemm128_kernel<3><<<gemm_blocks, TB>>>(nullptr, sW, sb, gb, M);
        // agg += edge messages
        edge_agg_kernel<<<agg_blocks, TB>>>(E);
        // h = mish(agg)
        mish_kernel<<<n4_blocks, TB>>>(n4);
    }

    // Postprocess
    post_kernel<<<post_blocks, TB>>>(W_post, b_post, out, M);
}

// round 9
// speedup vs baseline: 1.2700x; 1.0040x over previous
#include <cuda_runtime.h>
#include <math.h>

// Problem constants
#define NN    50000
#define NPAD  50176            // 392 * 128: full GEMM tiles, no store guards
#define EE    1600000
#define HDIM  128

// ---------------- static device scratch (allocation-free) ----------------
__device__ __align__(16) int   g_src[EE];
__device__ __align__(16) int   g_dst[EE];
__device__ __align__(16) float g_deg[NPAD];
__device__ __align__(16) float g_dis[NPAD];
__device__ __align__(16) float g_h  [(size_t)NPAD * HDIM];
__device__ __align__(16) float g_hg [(size_t)NPAD * HDIM];
__device__ __align__(16) float g_agg[(size_t)NPAD * HDIM];

// ---------------- math helpers ----------------
__device__ __forceinline__ float mishf(float x) {
    float sp = fmaxf(x, 0.0f) + log1pf(expf(-fabsf(x)));
    return x * tanhf(sp);
}
__device__ __forceinline__ void cp_async16(void* smem_dst, const void* gmem_src) {
    unsigned s = (unsigned)__cvta_generic_to_shared(smem_dst);
    asm volatile("cp.async.ca.shared.global [%0], [%1], 16;" :: "r"(s), "l"(gmem_src) : "memory");
}

// ---------------- small kernels ----------------
__global__ void init_deg_kernel(int n) {
    int i = blockIdx.x * blockDim.x + threadIdx.x;
    if (i < n) g_deg[i] = 1.0f;
}
__global__ void build_edges_kernel(const int* __restrict__ ei, int e, int n) {
    int i = blockIdx.x * blockDim.x + threadIdx.x;
    if (i < e) {
        int s = ei[i];
        int d = ei[e + i];
        if ((unsigned)s >= (unsigned)n) s = 0;
        if ((unsigned)d >= (unsigned)n) d = 0;
        g_src[i] = s;
        g_dst[i] = d;
        atomicAdd(&g_deg[d], 1.0f);
    }
}
__global__ void dis_kernel(int n) {
    int i = blockIdx.x * blockDim.x + threadIdx.x;
    if (i < n) g_dis[i] = rsqrtf(g_deg[i]);
}

// ---------------- preprocess SGEMM (round-4 proven config, KC=16) ----------------
// h = mish(x @ W_pre + b_pre)
__global__ __launch_bounds__(256) void pre_gemm_kernel(
    const float* __restrict__ A,
    const float* __restrict__ B,
    const float* __restrict__ bias,
    int M)
{
    const int K = 128, Ncols = 128;
    __shared__ float As[16][128];
    __shared__ float Bs[16][132];

    int tid = threadIdx.x;
    int block_row = blockIdx.x * 128;
    int tx = tid & 15;
    int ty = tid >> 4;

    float acc[8][8];
#pragma unroll
    for (int i = 0; i < 8; i++)
#pragma unroll
        for (int j = 0; j < 8; j++) acc[i][j] = 0.0f;

    for (int k0 = 0; k0 < K; k0 += 16) {
#pragma unroll
        for (int it = 0; it < 2; it++) {
            int f4 = tid + it * 256;
            int r  = f4 >> 2;
            int c  = (f4 & 3) * 4;
            int gr = block_row + r;
            float4 a = make_float4(0.f, 0.f, 0.f, 0.f);
            if (gr < M)
                a = *reinterpret_cast<const float4*>(A + (size_t)gr * K + k0 + c);
            As[c + 0][r] = a.x;
            As[c + 1][r] = a.y;
            As[c + 2][r] = a.z;
            As[c + 3][r] = a.w;
        }
#pragma unroll
        for (int it = 0; it < 2; it++) {
            int f4 = tid + it * 256;
            int r  = f4 >> 5;
            int c  = (f4 & 31) * 4;
            float4 b = *reinterpret_cast<const float4*>(B + (size_t)(k0 + r) * Ncols + c);
            *reinterpret_cast<float4*>(&Bs[r][c]) = b;
        }
        __syncthreads();

#pragma unroll
        for (int kk = 0; kk < 16; kk++) {
            float ra[8], rb[8];
            *reinterpret_cast<float4*>(ra)     = *reinterpret_cast<const float4*>(&As[kk][ty * 8]);
            *reinterpret_cast<float4*>(ra + 4) = *reinterpret_cast<const float4*>(&As[kk][ty * 8 + 4]);
            *reinterpret_cast<float4*>(rb)     = *reinterpret_cast<const float4*>(&Bs[kk][tx * 8]);
            *reinterpret_cast<float4*>(rb + 4) = *reinterpret_cast<const float4*>(&Bs[kk][tx * 8 + 4]);
#pragma unroll
            for (int i = 0; i < 8; i++)
#pragma unroll
                for (int j = 0; j < 8; j++)
                    acc[i][j] = fmaf(ra[i], rb[j], acc[i][j]);
        }
        __syncthreads();
    }

#pragma unroll
    for (int i = 0; i < 8; i++) {
        int gr = block_row + ty * 8 + i;
        float* crow = g_h + (size_t)gr * Ncols + tx * 8;
#pragma unroll
        for (int j = 0; j < 8; j++)
            crow[j] = mishf(acc[i][j] + bias[tx * 8 + j]);
    }
}

// ---------------- fused layer GEMM: barrier-free mainloop, B fully smem-resident ----
// Computes BOTH hg = h @ gcn_W (cols 0..127 -> g_hg raw) and
// agg = h @ skip_W + skip_b + gcn_b + dis^2*hg (cols 128..255 -> g_agg).
// 512 threads; each thread: 8 rows x 8 cols. lanes 0-15 own gcn cols, 16-31 skip cols.
// Self-loop term hg obtained from partner lane via shfl.
#define LDA2 132
#define LDB2 264
#define FUSED_SMEM ((128 * LDA2 + 128 * LDB2) * 4)   // 67584 + 135168 = 202752 B

__global__ __launch_bounds__(512, 1) void fused_layer_gemm(
    const float* __restrict__ gW,
    const float* __restrict__ sW,
    const float* __restrict__ gb,
    const float* __restrict__ sb)
{
    extern __shared__ float sm[];
    float* As = sm;                    // [128][LDA2], row-major (no transpose)
    float* Bs = sm + 128 * LDA2;       // [128][LDB2]: cols 0-127 gW, 128-255 sW

    int tid = threadIdx.x;
    int block_row = blockIdx.x * 128;
    int tx = tid & 31;                 // 32 col groups x 8 = 256 cols
    int ty = tid >> 5;                 // 16 row groups x 8 = 128 rows

    // Load B (both matrices) + A tile, all via cp.async, one barrier total.
#pragma unroll
    for (int it = 0; it < 8; it++) {
        int idx = tid + it * 512;      // 0..4095
        int r   = idx >> 5;            // 0..127
        int c   = (idx & 31) << 2;     // 0..124
        cp_async16(&Bs[r * LDB2 + c],       gW + (size_t)r * HDIM + c);
        cp_async16(&Bs[r * LDB2 + 128 + c], sW + (size_t)r * HDIM + c);
        cp_async16(&As[r * LDA2 + c], g_h + (size_t)(block_row + r) * HDIM + c);
    }
    asm volatile("cp.async.commit_group;" ::: "memory");
    asm volatile("cp.async.wait_group 0;" ::: "memory");
    __syncthreads();

    float acc[8][8];
#pragma unroll
    for (int i = 0; i < 8; i++)
#pragma unroll
        for (int j = 0; j < 8; j++) acc[i][j] = 0.0f;

    const float* arow = As + (ty * 8) * LDA2;   // 8 rows, stride LDA2

#pragma unroll 4
    for (int kk = 0; kk < 128; kk++) {
        float rb[8];
        *reinterpret_cast<float4*>(rb)     = *reinterpret_cast<const float4*>(&Bs[kk * LDB2 + tx * 8]);
        *reinterpret_cast<float4*>(rb + 4) = *reinterpret_cast<const float4*>(&Bs[kk * LDB2 + tx * 8 + 4]);
        float ra[8];
#pragma unroll
        for (int i = 0; i < 8; i++) ra[i] = arow[i * LDA2 + kk];   // broadcast LDS
#pragma unroll
        for (int i = 0; i < 8; i++)
#pragma unroll
            for (int j = 0; j < 8; j++)
                acc[i][j] = fmaf(ra[i], rb[j], acc[i][j]);
    }

    // Epilogue: lanes 0-15 -> g_hg raw; lanes 16-31 -> g_agg fused.
    int col = (tx & 15) * 8;
    float bsum[8];
    if (tx >= 16) {
#pragma unroll
        for (int j = 0; j < 8; j++) bsum[j] = gb[col + j] + sb[col + j];
    }
#pragma unroll
    for (int i = 0; i < 8; i++) {
        int gr = block_row + ty * 8 + i;
        float hgv[8];
#pragma unroll
        for (int j = 0; j < 8; j++)
            hgv[j] = __shfl_sync(0xFFFFFFFFu, acc[i][j], tx & 15);
        if (tx < 16) {
            float4* p = reinterpret_cast<float4*>(g_hg + (size_t)gr * HDIM + col);
            p[0] = make_float4(acc[i][0], acc[i][1], acc[i][2], acc[i][3]);
            p[1] = make_float4(acc[i][4], acc[i][5], acc[i][6], acc[i][7]);
        } else {
            float dis = g_dis[gr];
            float d2 = dis * dis;
            float o[8];
#pragma unroll
            for (int j = 0; j < 8; j++)
                o[j] = acc[i][j] + bsum[j] + d2 * hgv[j];
            float4* p = reinterpret_cast<float4*>(g_agg + (size_t)gr * HDIM + col);
            p[0] = make_float4(o[0], o[1], o[2], o[3]);
            p[1] = make_float4(o[4], o[5], o[6], o[7]);
        }
    }
}

// ---------------- edge aggregation: agg[dst] += dis[src]*dis[dst]*hg[src] ----------------
#define EPW 8
__global__ __launch_bounds__(256) void edge_agg_kernel(int e) {
    int gw   = (blockIdx.x * blockDim.x + threadIdx.x) >> 5;
    int lane = threadIdx.x & 31;
    int e0 = gw * EPW;
    if (e0 >= e) return;

    int   s[EPW], d[EPW];
    float n[EPW];
    float4 v[EPW];
    bool ok[EPW];
#pragma unroll
    for (int i = 0; i < EPW; i++) {
        int ed = e0 + i;
        ok[i] = ed < e;
        if (ok[i]) {
            s[i] = g_src[ed];
            d[i] = g_dst[ed];
            n[i] = g_dis[s[i]] * g_dis[d[i]];
            v[i] = *reinterpret_cast<const float4*>(g_hg + (size_t)s[i] * HDIM + lane * 4);
        }
    }
#pragma unroll
    for (int i = 0; i < EPW; i++) {
        if (ok[i]) {
            size_t ga = __cvta_generic_to_global(g_agg + (size_t)d[i] * HDIM + lane * 4);
            asm volatile("red.global.add.v4.f32 [%0], {%1, %2, %3, %4};"
                         :: "l"(ga),
                            "f"(v[i].x * n[i]), "f"(v[i].y * n[i]),
                            "f"(v[i].z * n[i]), "f"(v[i].w * n[i])
                         : "memory");
        }
    }
}

// ---------------- layer epilogue: h = mish(agg) ----------------
__global__ void mish_kernel(int n4) {
    int i = blockIdx.x * blockDim.x + threadIdx.x;
    if (i >= n4) return;
    float4 a = reinterpret_cast<const float4*>(g_agg)[i];
    float4 o;
    o.x = mishf(a.x);
    o.y = mishf(a.y);
    o.z = mishf(a.z);
    o.w = mishf(a.w);
    reinterpret_cast<float4*>(g_h)[i] = o;
}

// ---------------- post: out[i] = dot(h[i,:], W_post) + b_post ----------------
__global__ void post_kernel(const float* __restrict__ Wp,
                            const float* __restrict__ bp,
                            float* __restrict__ out, int M) {
    int warp = (blockIdx.x * blockDim.x + threadIdx.x) >> 5;
    int lane = threadIdx.x & 31;
    if (warp >= M) return;
    float4 hv = *reinterpret_cast<const float4*>(g_h + (size_t)warp * HDIM + lane * 4);
    float4 wv = *reinterpret_cast<const float4*>(Wp + lane * 4);
    float sum = hv.x * wv.x + hv.y * wv.y + hv.z * wv.z + hv.w * wv.w;
#pragma unroll
    for (int o = 16; o > 0; o >>= 1) sum += __shfl_xor_sync(0xFFFFFFFFu, sum, o);
    if (lane == 0) out[warp] = sum + bp[0];
}

// ---------------- launch ----------------
extern "C" void kernel_launch(void* const* d_in, const int* in_sizes, int n_in,
                              void* d_out, int out_size) {
    const float* x      = (const float*)d_in[0];
    const int*   ei     = (const int*)d_in[1];     // int32 (JAX x64-disabled)
    const float* W_pre  = (const float*)d_in[2];
    const float* b_pre  = (const float*)d_in[3];
    const float* gcn_W  = (const float*)d_in[4];
    const float* gcn_b  = (const float*)d_in[5];
    const float* skip_W = (const float*)d_in[6];
    const float* skip_b = (const float*)d_in[7];
    const float* W_post = (const float*)d_in[8];
    const float* b_post = (const float*)d_in[9];
    float*       out    = (float*)d_out;

    const int M = in_sizes[0] / HDIM;          // 50000
    const int E = in_sizes[1] / 2;             // 1600000
    const int L = in_sizes[4] / (HDIM * HDIM); // 3
    const int n4 = NPAD * (HDIM / 4);

    // allow 198 KB dynamic smem for the fused GEMM (attribute set, not an allocation)
    static bool attr_set = false;
    if (!attr_set) {
        cudaFuncSetAttribute(fused_layer_gemm,
                             cudaFuncAttributeMaxDynamicSharedMemorySize, FUSED_SMEM);
        attr_set = true;
    }

    const int TB = 256;
    const int gemm_blocks = NPAD / 128;        // 392
    const int node_blocks = (NPAD + TB - 1) / TB;
    const int edge_blocks = (E + TB - 1) / TB;
    const int n4_blocks   = (n4 + TB - 1) / TB;
    const int agg_warps   = (E + EPW - 1) / EPW;
    const int agg_blocks  = (agg_warps * 32 + TB - 1) / TB;
    const int post_blocks = (M * 32 + TB - 1) / TB;

    // Degrees + normalization (pad rows: deg=1 -> dis=1, harmless)
    init_deg_kernel<<<node_blocks, TB>>>(NPAD);
    build_edges_kernel<<<edge_blocks, TB>>>(ei, E, M);
    dis_kernel<<<node_blocks, TB>>>(NPAD);

    // Preprocess: h = mish(x @ W_pre + b_pre)
    pre_gemm_kernel<<<gemm_blocks, TB>>>(x, W_pre, b_pre, M);

    // GCN layers
    for (int l = 0; l < L; l++) {
        const float* gW = gcn_W  + (size_t)l * HDIM * HDIM;
        const float* sW = skip_W + (size_t)l * HDIM * HDIM;
        const float* gb = gcn_b  + (size_t)l * HDIM;
        const float* sb = skip_b + (size_t)l * HDIM;

        // g_hg = h @ gcn_W ; g_agg = h @ skip_W + sb + gb + dis^2*hg  (one kernel)
        fused_layer_gemm<<<gemm_blocks, 512, FUSED_SMEM>>>(gW, sW, gb, sb);
        // agg += edge messages
        edge_agg_kernel<<<agg_blocks, TB>>>(E);
        // h = mish(agg)
        mish_kernel<<<n4_blocks, TB>>>(n4);
    }

    // Postprocess
    post_kernel<<<post_blocks, TB>>>(W_post, b_post, out, M);
}

// round 10
// speedup vs baseline: 1.7551x; 1.3820x over previous
#include <cuda_runtime.h>
#include <math.h>

// Problem constants
#define NN    50000
#define NPAD  50176            // 392*128 full GEMM tiles; also 1024*49 for the scan
#define EE    1600000
#define HDIM  128

// ---------------- static device scratch (allocation-free) ----------------
__device__ __align__(16) int   g_icnt[NPAD];        // in-degree counts (no self-loop)
__device__ __align__(16) int   g_rowptr[NPAD + 1];
__device__ __align__(16) int   g_cur[NPAD];         // scatter cursors
__device__ __align__(16) int2  g_csr[EE];           // {src, norm-as-bits} grouped by dst
__device__ __align__(16) float g_dis[NPAD];
__device__ __align__(16) float g_h  [(size_t)NPAD * HDIM];
__device__ __align__(16) float g_hg [(size_t)NPAD * HDIM];
__device__ __align__(16) float g_agg[(size_t)NPAD * HDIM];

// ---------------- math helpers ----------------
__device__ __forceinline__ float mishf(float x) {
    float sp = fmaxf(x, 0.0f) + log1pf(expf(-fabsf(x)));
    return x * tanhf(sp);
}
__device__ __forceinline__ void cp_async16(void* smem_dst, const void* gmem_src) {
    unsigned s = (unsigned)__cvta_generic_to_shared(smem_dst);
    asm volatile("cp.async.ca.shared.global [%0], [%1], 16;" :: "r"(s), "l"(gmem_src) : "memory");
}

// ---------------- CSR build ----------------
__global__ void zero_cnt_kernel(int n) {
    int i = blockIdx.x * blockDim.x + threadIdx.x;
    if (i < n) g_icnt[i] = 0;
}
__global__ void count_kernel(const int* __restrict__ ei, int e, int n) {
    int i = blockIdx.x * blockDim.x + threadIdx.x;
    if (i < e) {
        int d = ei[e + i];
        if ((unsigned)d >= (unsigned)n) d = 0;
        atomicAdd(&g_icnt[d], 1);
    }
}
// exclusive scan over NPAD counts; single block, 1024 threads x 49 items
__global__ void scan_kernel() {
    __shared__ int part[1024];
    const int CH = NPAD / 1024;            // 49
    int t = threadIdx.x;
    int base = t * CH;
    int sum = 0;
    for (int i = 0; i < CH; i++) sum += g_icnt[base + i];
    part[t] = sum;
    __syncthreads();
    // Hillis-Steele inclusive scan
    for (int off = 1; off < 1024; off <<= 1) {
        int v = (t >= off) ? part[t - off] : 0;
        __syncthreads();
        part[t] += v;
        __syncthreads();
    }
    int run = part[t] - sum;               // exclusive prefix of this chunk
    for (int i = 0; i < CH; i++) {
        int c = g_icnt[base + i];
        g_rowptr[base + i] = run;
        g_cur[base + i]    = run;
        run += c;
    }
    if (t == 1023) g_rowptr[NPAD] = run;
}
__global__ void dis_kernel(int n) {
    int i = blockIdx.x * blockDim.x + threadIdx.x;
    if (i < n) g_dis[i] = rsqrtf(1.0f + (float)g_icnt[i]);   // +1 self-loop
}
__global__ void scatter_kernel(const int* __restrict__ ei, int e, int n) {
    int i = blockIdx.x * blockDim.x + threadIdx.x;
    if (i < e) {
        int s = ei[i];
        int d = ei[e + i];
        if ((unsigned)s >= (unsigned)n) s = 0;
        if ((unsigned)d >= (unsigned)n) d = 0;
        float norm = g_dis[s] * g_dis[d];
        int pos = atomicAdd(&g_cur[d], 1);
        g_csr[pos] = make_int2(s, __float_as_int(norm));
    }
}

// ---------------- preprocess SGEMM (proven config, KC=16) ----------------
__global__ __launch_bounds__(256) void pre_gemm_kernel(
    const float* __restrict__ A,
    const float* __restrict__ B,
    const float* __restrict__ bias,
    int M)
{
    const int K = 128, Ncols = 128;
    __shared__ float As[16][128];
    __shared__ float Bs[16][132];

    int tid = threadIdx.x;
    int block_row = blockIdx.x * 128;
    int tx = tid & 15;
    int ty = tid >> 4;

    float acc[8][8];
#pragma unroll
    for (int i = 0; i < 8; i++)
#pragma unroll
        for (int j = 0; j < 8; j++) acc[i][j] = 0.0f;

    for (int k0 = 0; k0 < K; k0 += 16) {
#pragma unroll
        for (int it = 0; it < 2; it++) {
            int f4 = tid + it * 256;
            int r  = f4 >> 2;
            int c  = (f4 & 3) * 4;
            int gr = block_row + r;
            float4 a = make_float4(0.f, 0.f, 0.f, 0.f);
            if (gr < M)
                a = *reinterpret_cast<const float4*>(A + (size_t)gr * K + k0 + c);
            As[c + 0][r] = a.x;
            As[c + 1][r] = a.y;
            As[c + 2][r] = a.z;
            As[c + 3][r] = a.w;
        }
#pragma unroll
        for (int it = 0; it < 2; it++) {
            int f4 = tid + it * 256;
            int r  = f4 >> 5;
            int c  = (f4 & 31) * 4;
            float4 b = *reinterpret_cast<const float4*>(B + (size_t)(k0 + r) * Ncols + c);
            *reinterpret_cast<float4*>(&Bs[r][c]) = b;
        }
        __syncthreads();

#pragma unroll
        for (int kk = 0; kk < 16; kk++) {
            float ra[8], rb[8];
            *reinterpret_cast<float4*>(ra)     = *reinterpret_cast<const float4*>(&As[kk][ty * 8]);
            *reinterpret_cast<float4*>(ra + 4) = *reinterpret_cast<const float4*>(&As[kk][ty * 8 + 4]);
            *reinterpret_cast<float4*>(rb)     = *reinterpret_cast<const float4*>(&Bs[kk][tx * 8]);
            *reinterpret_cast<float4*>(rb + 4) = *reinterpret_cast<const float4*>(&Bs[kk][tx * 8 + 4]);
#pragma unroll
            for (int i = 0; i < 8; i++)
#pragma unroll
                for (int j = 0; j < 8; j++)
                    acc[i][j] = fmaf(ra[i], rb[j], acc[i][j]);
        }
        __syncthreads();
    }

#pragma unroll
    for (int i = 0; i < 8; i++) {
        int gr = block_row + ty * 8 + i;
        float* crow = g_h + (size_t)gr * Ncols + tx * 8;
#pragma unroll
        for (int j = 0; j < 8; j++)
            crow[j] = mishf(acc[i][j] + bias[tx * 8 + j]);
    }
}

// ---------------- fused layer GEMM (round-9 proven): hg and agg-base in one pass ----
#define LDA2 132
#define LDB2 264
#define FUSED_SMEM ((128 * LDA2 + 128 * LDB2) * 4)   // 202752 B

__global__ __launch_bounds__(512, 1) void fused_layer_gemm(
    const float* __restrict__ gW,
    const float* __restrict__ sW,
    const float* __restrict__ gb,
    const float* __restrict__ sb)
{
    extern __shared__ float sm[];
    float* As = sm;
    float* Bs = sm + 128 * LDA2;

    int tid = threadIdx.x;
    int block_row = blockIdx.x * 128;
    int tx = tid & 31;
    int ty = tid >> 5;

#pragma unroll
    for (int it = 0; it < 8; it++) {
        int idx = tid + it * 512;
        int r   = idx >> 5;
        int c   = (idx & 31) << 2;
        cp_async16(&Bs[r * LDB2 + c],       gW + (size_t)r * HDIM + c);
        cp_async16(&Bs[r * LDB2 + 128 + c], sW + (size_t)r * HDIM + c);
        cp_async16(&As[r * LDA2 + c], g_h + (size_t)(block_row + r) * HDIM + c);
    }
    asm volatile("cp.async.commit_group;" ::: "memory");
    asm volatile("cp.async.wait_group 0;" ::: "memory");
    __syncthreads();

    float acc[8][8];
#pragma unroll
    for (int i = 0; i < 8; i++)
#pragma unroll
        for (int j = 0; j < 8; j++) acc[i][j] = 0.0f;

    const float* arow = As + (ty * 8) * LDA2;

#pragma unroll 4
    for (int kk = 0; kk < 128; kk++) {
        float rb[8];
        *reinterpret_cast<float4*>(rb)     = *reinterpret_cast<const float4*>(&Bs[kk * LDB2 + tx * 8]);
        *reinterpret_cast<float4*>(rb + 4) = *reinterpret_cast<const float4*>(&Bs[kk * LDB2 + tx * 8 + 4]);
        float ra[8];
#pragma unroll
        for (int i = 0; i < 8; i++) ra[i] = arow[i * LDA2 + kk];
#pragma unroll
        for (int i = 0; i < 8; i++)
#pragma unroll
            for (int j = 0; j < 8; j++)
                acc[i][j] = fmaf(ra[i], rb[j], acc[i][j]);
    }

    int col = (tx & 15) * 8;
    float bsum[8];
    if (tx >= 16) {
#pragma unroll
        for (int j = 0; j < 8; j++) bsum[j] = gb[col + j] + sb[col + j];
    }
#pragma unroll
    for (int i = 0; i < 8; i++) {
        int gr = block_row + ty * 8 + i;
        float hgv[8];
#pragma unroll
        for (int j = 0; j < 8; j++)
            hgv[j] = __shfl_sync(0xFFFFFFFFu, acc[i][j], tx & 15);
        if (tx < 16) {
            float4* p = reinterpret_cast<float4*>(g_hg + (size_t)gr * HDIM + col);
            p[0] = make_float4(acc[i][0], acc[i][1], acc[i][2], acc[i][3]);
            p[1] = make_float4(acc[i][4], acc[i][5], acc[i][6], acc[i][7]);
        } else {
            float dis = g_dis[gr];
            float d2 = dis * dis;
            float o[8];
#pragma unroll
            for (int j = 0; j < 8; j++)
                o[j] = acc[i][j] + bsum[j] + d2 * hgv[j];
            float4* p = reinterpret_cast<float4*>(g_agg + (size_t)gr * HDIM + col);
            p[0] = make_float4(o[0], o[1], o[2], o[3]);
            p[1] = make_float4(o[4], o[5], o[6], o[7]);
        }
    }
}

// ---------------- CSR pull aggregation + fused mish ----------------
// warp per dst node: h[v] = mish(agg_base[v] + sum_j norm_j * hg[src_j])
__global__ __launch_bounds__(256) void csr_agg_kernel() {
    int warp = (blockIdx.x * blockDim.x + threadIdx.x) >> 5;
    int lane = threadIdx.x & 31;
    if (warp >= NPAD) return;

    float4 acc = *reinterpret_cast<const float4*>(g_agg + (size_t)warp * HDIM + lane * 4);
    int base = g_rowptr[warp];
    int end  = g_rowptr[warp + 1];

    int j = base;
    for (; j + 4 <= end; j += 4) {
        int2 e0 = __ldg(&g_csr[j + 0]);
        int2 e1 = __ldg(&g_csr[j + 1]);
        int2 e2 = __ldg(&g_csr[j + 2]);
        int2 e3 = __ldg(&g_csr[j + 3]);
        float4 v0 = *reinterpret_cast<const float4*>(g_hg + (size_t)e0.x * HDIM + lane * 4);
        float4 v1 = *reinterpret_cast<const float4*>(g_hg + (size_t)e1.x * HDIM + lane * 4);
        float4 v2 = *reinterpret_cast<const float4*>(g_hg + (size_t)e2.x * HDIM + lane * 4);
        float4 v3 = *reinterpret_cast<const float4*>(g_hg + (size_t)e3.x * HDIM + lane * 4);
        float n0 = __int_as_float(e0.y), n1 = __int_as_float(e1.y);
        float n2 = __int_as_float(e2.y), n3 = __int_as_float(e3.y);
        acc.x = fmaf(n0, v0.x, acc.x); acc.y = fmaf(n0, v0.y, acc.y);
        acc.z = fmaf(n0, v0.z, acc.z); acc.w = fmaf(n0, v0.w, acc.w);
        acc.x = fmaf(n1, v1.x, acc.x); acc.y = fmaf(n1, v1.y, acc.y);
        acc.z = fmaf(n1, v1.z, acc.z); acc.w = fmaf(n1, v1.w, acc.w);
        acc.x = fmaf(n2, v2.x, acc.x); acc.y = fmaf(n2, v2.y, acc.y);
        acc.z = fmaf(n2, v2.z, acc.z); acc.w = fmaf(n2, v2.w, acc.w);
        acc.x = fmaf(n3, v3.x, acc.x); acc.y = fmaf(n3, v3.y, acc.y);
        acc.z = fmaf(n3, v3.z, acc.z); acc.w = fmaf(n3, v3.w, acc.w);
    }
    for (; j < end; j++) {
        int2 e = __ldg(&g_csr[j]);
        float4 v = *reinterpret_cast<const float4*>(g_hg + (size_t)e.x * HDIM + lane * 4);
        float n = __int_as_float(e.y);
        acc.x = fmaf(n, v.x, acc.x); acc.y = fmaf(n, v.y, acc.y);
        acc.z = fmaf(n, v.z, acc.z); acc.w = fmaf(n, v.w, acc.w);
    }

    float4 o;
    o.x = mishf(acc.x);
    o.y = mishf(acc.y);
    o.z = mishf(acc.z);
    o.w = mishf(acc.w);
    *reinterpret_cast<float4*>(g_h + (size_t)warp * HDIM + lane * 4) = o;
}

// ---------------- post: out[i] = dot(h[i,:], W_post) + b_post ----------------
__global__ void post_kernel(const float* __restrict__ Wp,
                            const float* __restrict__ bp,
                            float* __restrict__ out, int M) {
    int warp = (blockIdx.x * blockDim.x + threadIdx.x) >> 5;
    int lane = threadIdx.x & 31;
    if (warp >= M) return;
    float4 hv = *reinterpret_cast<const float4*>(g_h + (size_t)warp * HDIM + lane * 4);
    float4 wv = *reinterpret_cast<const float4*>(Wp + lane * 4);
    float sum = hv.x * wv.x + hv.y * wv.y + hv.z * wv.z + hv.w * wv.w;
#pragma unroll
    for (int o = 16; o > 0; o >>= 1) sum += __shfl_xor_sync(0xFFFFFFFFu, sum, o);
    if (lane == 0) out[warp] = sum + bp[0];
}

// ---------------- launch ----------------
extern "C" void kernel_launch(void* const* d_in, const int* in_sizes, int n_in,
                              void* d_out, int out_size) {
    const float* x      = (const float*)d_in[0];
    const int*   ei     = (const int*)d_in[1];     // int32 (JAX x64-disabled)
    const float* W_pre  = (const float*)d_in[2];
    const float* b_pre  = (const float*)d_in[3];
    const float* gcn_W  = (const float*)d_in[4];
    const float* gcn_b  = (const float*)d_in[5];
    const float* skip_W = (const float*)d_in[6];
    const float* skip_b = (const float*)d_in[7];
    const float* W_post = (const float*)d_in[8];
    const float* b_post = (const float*)d_in[9];
    float*       out    = (float*)d_out;

    const int M = in_sizes[0] / HDIM;          // 50000
    const int E = in_sizes[1] / 2;             // 1600000
    const int L = in_sizes[4] / (HDIM * HDIM); // 3

    cudaFuncSetAttribute(fused_layer_gemm,
                         cudaFuncAttributeMaxDynamicSharedMemorySize, FUSED_SMEM);

    const int TB = 256;
    const int gemm_blocks = NPAD / 128;            // 392
    const int node_blocks = (NPAD + TB - 1) / TB;
    const int edge_blocks = (E + TB - 1) / TB;
    const int aggw_blocks = (NPAD * 32) / TB;      // warp per node
    const int post_blocks = (M * 32 + TB - 1) / TB;

    // ---- CSR build (once; reused across layers) ----
    zero_cnt_kernel<<<node_blocks, TB>>>(NPAD);
    count_kernel<<<edge_blocks, TB>>>(ei, E, M);
    scan_kernel<<<1, 1024>>>();
    dis_kernel<<<node_blocks, TB>>>(NPAD);
    scatter_kernel<<<edge_blocks, TB>>>(ei, E, M);

    // Preprocess: h = mish(x @ W_pre + b_pre)
    pre_gemm_kernel<<<gemm_blocks, TB>>>(x, W_pre, b_pre, M);

    // GCN layers
    for (int l = 0; l < L; l++) {
        const float* gW = gcn_W  + (size_t)l * HDIM * HDIM;
        const float* sW = skip_W + (size_t)l * HDIM * HDIM;
        const float* gb = gcn_b  + (size_t)l * HDIM;
        const float* sb = skip_b + (size_t)l * HDIM;

        fused_layer_gemm<<<gemm_blocks, 512, FUSED_SMEM>>>(gW, sW, gb, sb);
        csr_agg_kernel<<<aggw_blocks, TB>>>();
    }

    // Postprocess
    post_kernel<<<post_blocks, TB>>>(W_post, b_post, out, M);
}

// round 11
// speedup vs baseline: 2.2980x; 1.3093x over previous
#include <cuda_runtime.h>
#include <cuda_bf16.h>
#include <math.h>
#include <mma.h>

using namespace nvcuda;

// Problem constants
#define NN    50000
#define NPAD  50176            // 392*128 full GEMM tiles; 1024*49 for the scan
#define EE    1600000
#define HDIM  128

// ---------------- static device scratch (allocation-free) ----------------
__device__ __align__(16) int   g_icnt[NPAD];
__device__ __align__(16) int   g_rowptr[NPAD + 1];
__device__ __align__(16) int   g_cur[NPAD];
__device__ __align__(16) int2  g_csr[EE];           // {src, norm-bits} grouped by dst
__device__ __align__(16) float g_dis[NPAD];
__device__ __align__(16) float g_h  [(size_t)NPAD * HDIM];
__device__ __align__(16) float g_hg [(size_t)NPAD * HDIM];
__device__ __align__(16) float g_agg[(size_t)NPAD * HDIM];
// bf16 hi/lo operand images
__device__ __align__(16) __nv_bfloat16 g_ahi[(size_t)NPAD * HDIM];
__device__ __align__(16) __nv_bfloat16 g_alo[(size_t)NPAD * HDIM];
// weight slots: slot 0 = W_pre (cols 0-127); slot 1+l = [gcn_W_l | skip_W_l] (256 cols)
__device__ __align__(16) __nv_bfloat16 g_whi[(size_t)4 * HDIM * 256];
__device__ __align__(16) __nv_bfloat16 g_wlo[(size_t)4 * HDIM * 256];

// ---------------- math helpers ----------------
__device__ __forceinline__ float mishf(float x) {
    float sp = fmaxf(x, 0.0f) + log1pf(expf(-fabsf(x)));
    return x * tanhf(sp);
}
__device__ __forceinline__ void bsplit(float x, __nv_bfloat16& h, __nv_bfloat16& l) {
    h = __float2bfloat16_rn(x);
    l = __float2bfloat16_rn(x - __bfloat162float(h));
}
__device__ __forceinline__ void cp_async16(void* smem_dst, const void* gmem_src) {
    unsigned s = (unsigned)__cvta_generic_to_shared(smem_dst);
    asm volatile("cp.async.ca.shared.global [%0], [%1], 16;" :: "r"(s), "l"(gmem_src) : "memory");
}

// ---------------- CSR build ----------------
__global__ void zero_cnt_kernel(int n) {
    int i = blockIdx.x * blockDim.x + threadIdx.x;
    if (i < n) g_icnt[i] = 0;
}
__global__ void count_kernel(const int* __restrict__ ei, int e, int n) {
    int i = blockIdx.x * blockDim.x + threadIdx.x;
    if (i < e) {
        int d = ei[e + i];
        if ((unsigned)d >= (unsigned)n) d = 0;
        atomicAdd(&g_icnt[d], 1);
    }
}
__global__ void scan_kernel() {
    __shared__ int part[1024];
    const int CH = NPAD / 1024;            // 49
    int t = threadIdx.x;
    int base = t * CH;
    int sum = 0;
    for (int i = 0; i < CH; i++) sum += g_icnt[base + i];
    part[t] = sum;
    __syncthreads();
    for (int off = 1; off < 1024; off <<= 1) {
        int v = (t >= off) ? part[t - off] : 0;
        __syncthreads();
        part[t] += v;
        __syncthreads();
    }
    int run = part[t] - sum;
    for (int i = 0; i < CH; i++) {
        int c = g_icnt[base + i];
        g_rowptr[base + i] = run;
        g_cur[base + i]    = run;
        run += c;
    }
    if (t == 1023) g_rowptr[NPAD] = run;
}
__global__ void dis_kernel(int n) {
    int i = blockIdx.x * blockDim.x + threadIdx.x;
    if (i < n) g_dis[i] = rsqrtf(1.0f + (float)g_icnt[i]);
}
__global__ void scatter_kernel(const int* __restrict__ ei, int e, int n) {
    int i = blockIdx.x * blockDim.x + threadIdx.x;
    if (i < e) {
        int s = ei[i];
        int d = ei[e + i];
        if ((unsigned)s >= (unsigned)n) s = 0;
        if ((unsigned)d >= (unsigned)n) d = 0;
        float norm = g_dis[s] * g_dis[d];
        int pos = atomicAdd(&g_cur[d], 1);
        g_csr[pos] = make_int2(s, __float_as_int(norm));
    }
}

// ---------------- operand prep ----------------
__global__ void split_x_kernel(const float* __restrict__ x, int M, int ntot) {
    int i = blockIdx.x * blockDim.x + threadIdx.x;
    if (i >= ntot) return;
    int row = i >> 7;
    float v = (row < M) ? x[i] : 0.0f;
    bsplit(v, g_ahi[i], g_alo[i]);
}
// split one 128x128 weight into (slot, colOff) of the 256-wide slot layout
__global__ void split_w_kernel(const float* __restrict__ W, int slot, int colOff) {
    int i = blockIdx.x * blockDim.x + threadIdx.x;
    if (i >= HDIM * HDIM) return;
    int r = i >> 7, c = i & 127;
    size_t o = (size_t)slot * HDIM * 256 + (size_t)r * 256 + colOff + c;
    bsplit(W[i], g_whi[o], g_wlo[o]);
}

// ---------------- wmma bf16 3-term GEMM, fully smem-resident, barrier-free ----------
// C[128-row tile, NCOLS] = (Ahi+Alo) @ (Bhi+Blo); D += Ah*Bh + Ah*Bl + Al*Bh
// MODE 0 (pre): all cols -> g_hg raw
// MODE 1 (fused layer): cols 0-127 -> g_hg raw, cols 128-255 -> g_agg raw
#define LDA3 136
template <int NCOLS, int MODE>
__global__ __launch_bounds__(512, 1) void wmma_gemm(int slot) {
    extern __shared__ __nv_bfloat16 sm[];
    const int LDB3 = NCOLS + 8;
    const int ASZ = 128 * LDA3;
    const int BSZ = 128 * LDB3;
    __nv_bfloat16* Ah = sm;
    __nv_bfloat16* Al = sm + ASZ;
    __nv_bfloat16* Bh = sm + 2 * ASZ;
    __nv_bfloat16* Bl = sm + 2 * ASZ + BSZ;

    int tid = threadIdx.x;
    int warp = tid >> 5;
    int wm = warp & 3;                 // 4 row bands of 32
    int wn = warp >> 2;                // 4 col bands of NCOLS/4
    int block_row = blockIdx.x * 128;

    // Fill A (128 x 128 bf16 hi/lo)
    for (int idx = tid; idx < 128 * 16; idx += 512) {
        int r = idx >> 4;
        int c8 = (idx & 15) << 3;
        size_t go = (size_t)(block_row + r) * HDIM + c8;
        cp_async16(&Ah[r * LDA3 + c8], g_ahi + go);
        cp_async16(&Al[r * LDA3 + c8], g_alo + go);
    }
    // Fill B (128 x NCOLS bf16 hi/lo) from the 256-stride slot
    for (int idx = tid; idx < 128 * (NCOLS / 8); idx += 512) {
        int r = idx / (NCOLS / 8);
        int c8 = (idx % (NCOLS / 8)) << 3;
        size_t go = (size_t)slot * HDIM * 256 + (size_t)r * 256 + c8;
        cp_async16(&Bh[r * LDB3 + c8], g_whi + go);
        cp_async16(&Bl[r * LDB3 + c8], g_wlo + go);
    }
    asm volatile("cp.async.commit_group;" ::: "memory");
    asm volatile("cp.async.wait_group 0;" ::: "memory");
    __syncthreads();

    constexpr int NB = NCOLS / 64;     // b-frags per warp (256->4, 128->2)
    wmma::fragment<wmma::accumulator, 16, 16, 16, float> acc[2][NB];
#pragma unroll
    for (int i = 0; i < 2; i++)
#pragma unroll
        for (int j = 0; j < NB; j++) wmma::fill_fragment(acc[i][j], 0.0f);

    int cbase = wn * (NCOLS / 4);

#pragma unroll
    for (int k = 0; k < 8; k++) {
        wmma::fragment<wmma::matrix_a, 16, 16, 16, __nv_bfloat16, wmma::row_major> ah[2], al[2];
        wmma::fragment<wmma::matrix_b, 16, 16, 16, __nv_bfloat16, wmma::row_major> bh[NB], bl[NB];
#pragma unroll
        for (int i = 0; i < 2; i++) {
            wmma::load_matrix_sync(ah[i], &Ah[(wm * 32 + i * 16) * LDA3 + k * 16], LDA3);
            wmma::load_matrix_sync(al[i], &Al[(wm * 32 + i * 16) * LDA3 + k * 16], LDA3);
        }
#pragma unroll
        for (int j = 0; j < NB; j++) {
            wmma::load_matrix_sync(bh[j], &Bh[(k * 16) * LDB3 + cbase + j * 16], LDB3);
            wmma::load_matrix_sync(bl[j], &Bl[(k * 16) * LDB3 + cbase + j * 16], LDB3);
        }
#pragma unroll
        for (int i = 0; i < 2; i++)
#pragma unroll
            for (int j = 0; j < NB; j++) {
                wmma::mma_sync(acc[i][j], ah[i], bh[j], acc[i][j]);
                wmma::mma_sync(acc[i][j], ah[i], bl[j], acc[i][j]);
                wmma::mma_sync(acc[i][j], al[i], bh[j], acc[i][j]);
            }
    }

#pragma unroll
    for (int i = 0; i < 2; i++)
#pragma unroll
        for (int j = 0; j < NB; j++) {
            int gr = block_row + wm * 32 + i * 16;
            int gc = cbase + j * 16;
            float* dst;
            if (MODE == 0 || gc < 128)
                dst = g_hg + (size_t)gr * HDIM + gc;
            else
                dst = g_agg + (size_t)gr * HDIM + (gc - 128);
            wmma::store_matrix_sync(dst, acc[i][j], HDIM, wmma::mem_row_major);
        }
}

// ---------------- pre activation: h = mish(t + b_pre); emit fp32 + bf16 split ----
__global__ void pre_act_kernel(const float* __restrict__ bias, int n4) {
    int i = blockIdx.x * blockDim.x + threadIdx.x;
    if (i >= n4) return;
    int c4 = i & 31;
    float4 t = reinterpret_cast<const float4*>(g_hg)[i];
    float4 b = reinterpret_cast<const float4*>(bias)[c4];
    float4 o;
    o.x = mishf(t.x + b.x);
    o.y = mishf(t.y + b.y);
    o.z = mishf(t.z + b.z);
    o.w = mishf(t.w + b.w);
    reinterpret_cast<float4*>(g_h)[i] = o;
    int e = i * 4;
    bsplit(o.x, g_ahi[e + 0], g_alo[e + 0]);
    bsplit(o.y, g_ahi[e + 1], g_alo[e + 1]);
    bsplit(o.z, g_ahi[e + 2], g_alo[e + 2]);
    bsplit(o.w, g_ahi[e + 3], g_alo[e + 3]);
}

// ---------------- CSR pull aggregation + biases + self-loop + mish + split ---------
// h[v] = mish(agg[v] + gb + sb + dis[v]^2*hg[v] + sum_j norm_j * hg[src_j])
__global__ __launch_bounds__(256) void csr_agg_kernel(const float* __restrict__ gb,
                                                      const float* __restrict__ sb) {
    int warp = (blockIdx.x * blockDim.x + threadIdx.x) >> 5;
    int lane = threadIdx.x & 31;
    if (warp >= NPAD) return;

    float4 acc = *reinterpret_cast<const float4*>(g_agg + (size_t)warp * HDIM + lane * 4);
    {
        float4 b1 = *reinterpret_cast<const float4*>(gb + lane * 4);
        float4 b2 = *reinterpret_cast<const float4*>(sb + lane * 4);
        float4 hv = *reinterpret_cast<const float4*>(g_hg + (size_t)warp * HDIM + lane * 4);
        float dis = g_dis[warp];
        float d2 = dis * dis;
        acc.x += b1.x + b2.x + d2 * hv.x;
        acc.y += b1.y + b2.y + d2 * hv.y;
        acc.z += b1.z + b2.z + d2 * hv.z;
        acc.w += b1.w + b2.w + d2 * hv.w;
    }
    int base = g_rowptr[warp];
    int end  = g_rowptr[warp + 1];

    int j = base;
    for (; j + 4 <= end; j += 4) {
        int2 e0 = __ldg(&g_csr[j + 0]);
        int2 e1 = __ldg(&g_csr[j + 1]);
        int2 e2 = __ldg(&g_csr[j + 2]);
        int2 e3 = __ldg(&g_csr[j + 3]);
        float4 v0 = *reinterpret_cast<const float4*>(g_hg + (size_t)e0.x * HDIM + lane * 4);
        float4 v1 = *reinterpret_cast<const float4*>(g_hg + (size_t)e1.x * HDIM + lane * 4);
        float4 v2 = *reinterpret_cast<const float4*>(g_hg + (size_t)e2.x * HDIM + lane * 4);
        float4 v3 = *reinterpret_cast<const float4*>(g_hg + (size_t)e3.x * HDIM + lane * 4);
        float n0 = __int_as_float(e0.y), n1 = __int_as_float(e1.y);
        float n2 = __int_as_float(e2.y), n3 = __int_as_float(e3.y);
        acc.x = fmaf(n0, v0.x, acc.x); acc.y = fmaf(n0, v0.y, acc.y);
        acc.z = fmaf(n0, v0.z, acc.z); acc.w = fmaf(n0, v0.w, acc.w);
        acc.x = fmaf(n1, v1.x, acc.x); acc.y = fmaf(n1, v1.y, acc.y);
        acc.z = fmaf(n1, v1.z, acc.z); acc.w = fmaf(n1, v1.w, acc.w);
        acc.x = fmaf(n2, v2.x, acc.x); acc.y = fmaf(n2, v2.y, acc.y);
        acc.z = fmaf(n2, v2.z, acc.z); acc.w = fmaf(n2, v2.w, acc.w);
        acc.x = fmaf(n3, v3.x, acc.x); acc.y = fmaf(n3, v3.y, acc.y);
        acc.z = fmaf(n3, v3.z, acc.z); acc.w = fmaf(n3, v3.w, acc.w);
    }
    for (; j < end; j++) {
        int2 e = __ldg(&g_csr[j]);
        float4 v = *reinterpret_cast<const float4*>(g_hg + (size_t)e.x * HDIM + lane * 4);
        float n = __int_as_float(e.y);
        acc.x = fmaf(n, v.x, acc.x); acc.y = fmaf(n, v.y, acc.y);
        acc.z = fmaf(n, v.z, acc.z); acc.w = fmaf(n, v.w, acc.w);
    }

    float4 o;
    o.x = mishf(acc.x);
    o.y = mishf(acc.y);
    o.z = mishf(acc.z);
    o.w = mishf(acc.w);
    size_t fo = (size_t)warp * HDIM + lane * 4;
    *reinterpret_cast<float4*>(g_h + fo) = o;
    bsplit(o.x, g_ahi[fo + 0], g_alo[fo + 0]);
    bsplit(o.y, g_ahi[fo + 1], g_alo[fo + 1]);
    bsplit(o.z, g_ahi[fo + 2], g_alo[fo + 2]);
    bsplit(o.w, g_ahi[fo + 3], g_alo[fo + 3]);
}

// ---------------- post: out[i] = dot(h[i,:], W_post) + b_post ----------------
__global__ void post_kernel(const float* __restrict__ Wp,
                            const float* __restrict__ bp,
                            float* __restrict__ out, int M) {
    int warp = (blockIdx.x * blockDim.x + threadIdx.x) >> 5;
    int lane = threadIdx.x & 31;
    if (warp >= M) return;
    float4 hv = *reinterpret_cast<const float4*>(g_h + (size_t)warp * HDIM + lane * 4);
    float4 wv = *reinterpret_cast<const float4*>(Wp + lane * 4);
    float sum = hv.x * wv.x + hv.y * wv.y + hv.z * wv.z + hv.w * wv.w;
#pragma unroll
    for (int o = 16; o > 0; o >>= 1) sum += __shfl_xor_sync(0xFFFFFFFFu, sum, o);
    if (lane == 0) out[warp] = sum + bp[0];
}

// ---------------- launch ----------------
#define PRE_SMEM   ((2 * 128 * LDA3 + 2 * 128 * 136) * 2)   // A hi/lo + B(128) hi/lo
#define FUSED_SMEM ((2 * 128 * LDA3 + 2 * 128 * 264) * 2)   // A hi/lo + B(256) hi/lo

extern "C" void kernel_launch(void* const* d_in, const int* in_sizes, int n_in,
                              void* d_out, int out_size) {
    const float* x      = (const float*)d_in[0];
    const int*   ei     = (const int*)d_in[1];     // int32 (JAX x64-disabled)
    const float* W_pre  = (const float*)d_in[2];
    const float* b_pre  = (const float*)d_in[3];
    const float* gcn_W  = (const float*)d_in[4];
    const float* gcn_b  = (const float*)d_in[5];
    const float* skip_W = (const float*)d_in[6];
    const float* skip_b = (const float*)d_in[7];
    const float* W_post = (const float*)d_in[8];
    const float* b_post = (const float*)d_in[9];
    float*       out    = (float*)d_out;

    const int M = in_sizes[0] / HDIM;          // 50000
    const int E = in_sizes[1] / 2;             // 1600000
    const int L = in_sizes[4] / (HDIM * HDIM); // 3
    const int n4 = NPAD * (HDIM / 4);
    const int ntot = NPAD * HDIM;

    cudaFuncSetAttribute(wmma_gemm<128, 0>,
                         cudaFuncAttributeMaxDynamicSharedMemorySize, PRE_SMEM);
    cudaFuncSetAttribute(wmma_gemm<256, 1>,
                         cudaFuncAttributeMaxDynamicSharedMemorySize, FUSED_SMEM);

    const int TB = 256;
    const int gemm_blocks = NPAD / 128;            // 392
    const int node_blocks = (NPAD + TB - 1) / TB;
    const int edge_blocks = (E + TB - 1) / TB;
    const int n4_blocks   = (n4 + TB - 1) / TB;
    const int nt_blocks   = (ntot + TB - 1) / TB;
    const int w_blocks    = (HDIM * HDIM + TB - 1) / TB;
    const int aggw_blocks = (NPAD * 32) / TB;
    const int post_blocks = (M * 32 + TB - 1) / TB;

    // ---- CSR build (once) ----
    zero_cnt_kernel<<<node_blocks, TB>>>(NPAD);
    count_kernel<<<edge_blocks, TB>>>(ei, E, M);
    scan_kernel<<<1, 1024>>>();
    dis_kernel<<<node_blocks, TB>>>(NPAD);
    scatter_kernel<<<edge_blocks, TB>>>(ei, E, M);

    // ---- weight split (once) ----
    split_w_kernel<<<w_blocks, TB>>>(W_pre, 0, 0);
    for (int l = 0; l < L; l++) {
        split_w_kernel<<<w_blocks, TB>>>(gcn_W  + (size_t)l * HDIM * HDIM, 1 + l, 0);
        split_w_kernel<<<w_blocks, TB>>>(skip_W + (size_t)l * HDIM * HDIM, 1 + l, 128);
    }

    // ---- preprocess: t = x @ W_pre; h = mish(t + b_pre) ----
    split_x_kernel<<<nt_blocks, TB>>>(x, M, ntot);
    wmma_gemm<128, 0><<<gemm_blocks, 512, PRE_SMEM>>>(0);
    pre_act_kernel<<<n4_blocks, TB>>>(b_pre, n4);

    // ---- GCN layers ----
    for (int l = 0; l < L; l++) {
        const float* gb = gcn_b  + (size_t)l * HDIM;
        const float* sb = skip_b + (size_t)l * HDIM;
        wmma_gemm<256, 1><<<gemm_blocks, 512, FUSED_SMEM>>>(1 + l);
        csr_agg_kernel<<<aggw_blocks, TB>>>(gb, sb);
    }

    // ---- postprocess ----
    post_kernel<<<post_blocks, TB>>>(W_post, b_post, out, M);
}

// round 12
// speedup vs baseline: 2.5683x; 1.1176x over previous
#include <cuda_runtime.h>
#include <cuda_bf16.h>
#include <math.h>
#include <mma.h>

using namespace nvcuda;

// Problem constants
#define NN    50000
#define NPAD  50176            // 392*128 full GEMM tiles; 1024*49 for the scan
#define EE    1600000
#define HDIM  128

// ---------------- static device scratch (allocation-free) ----------------
__device__ __align__(16) int   g_icnt[NPAD];
__device__ __align__(16) int   g_rowptr[NPAD + 1];
__device__ __align__(16) int   g_cur[NPAD];
__device__ __align__(16) int2  g_csr[EE];           // {src, norm-bits} grouped by dst
__device__ __align__(16) float g_dis[NPAD];
__device__ __align__(16) float g_h  [(size_t)NPAD * HDIM];
__device__ __align__(16) float g_hg [(size_t)NPAD * HDIM];
__device__ __align__(16) float g_agg[(size_t)NPAD * HDIM];
// bf16 hi/lo operand images
__device__ __align__(16) __nv_bfloat16 g_ahi[(size_t)NPAD * HDIM];
__device__ __align__(16) __nv_bfloat16 g_alo[(size_t)NPAD * HDIM];
// weight slots: slot 0 = W_pre (cols 0-127); slot 1+l = [gcn_W_l | skip_W_l] (256 cols)
__device__ __align__(16) __nv_bfloat16 g_whi[(size_t)4 * HDIM * 256];
__device__ __align__(16) __nv_bfloat16 g_wlo[(size_t)4 * HDIM * 256];

// ---------------- math helpers ----------------
__device__ __forceinline__ float mishf(float x) {
    float sp = fmaxf(x, 0.0f) + log1pf(expf(-fabsf(x)));
    return x * tanhf(sp);
}
__device__ __forceinline__ void bsplit(float x, __nv_bfloat16& h, __nv_bfloat16& l) {
    h = __float2bfloat16_rn(x);
    l = __float2bfloat16_rn(x - __bfloat162float(h));
}
__device__ __forceinline__ void cp_async16(void* smem_dst, const void* gmem_src) {
    unsigned s = (unsigned)__cvta_generic_to_shared(smem_dst);
    asm volatile("cp.async.ca.shared.global [%0], [%1], 16;" :: "r"(s), "l"(gmem_src) : "memory");
}

// ---------------- CSR build ----------------
__global__ void zero_cnt_kernel(int n) {
    int i = blockIdx.x * blockDim.x + threadIdx.x;
    if (i < n) g_icnt[i] = 0;
}
__global__ void count_kernel(const int* __restrict__ ei, int e, int n) {
    int i = blockIdx.x * blockDim.x + threadIdx.x;
    if (i < e) {
        int d = ei[e + i];
        if ((unsigned)d >= (unsigned)n) d = 0;
        atomicAdd(&g_icnt[d], 1);
    }
}
__global__ void scan_kernel() {
    __shared__ int part[1024];
    const int CH = NPAD / 1024;            // 49
    int t = threadIdx.x;
    int base = t * CH;
    int sum = 0;
    for (int i = 0; i < CH; i++) sum += g_icnt[base + i];
    part[t] = sum;
    __syncthreads();
    for (int off = 1; off < 1024; off <<= 1) {
        int v = (t >= off) ? part[t - off] : 0;
        __syncthreads();
        part[t] += v;
        __syncthreads();
    }
    int run = part[t] - sum;
    for (int i = 0; i < CH; i++) {
        int c = g_icnt[base + i];
        g_rowptr[base + i] = run;
        g_cur[base + i]    = run;
        run += c;
    }
    if (t == 1023) g_rowptr[NPAD] = run;
}
__global__ void dis_kernel(int n) {
    int i = blockIdx.x * blockDim.x + threadIdx.x;
    if (i < n) g_dis[i] = rsqrtf(1.0f + (float)g_icnt[i]);
}
__global__ void scatter_kernel(const int* __restrict__ ei, int e, int n) {
    int i = blockIdx.x * blockDim.x + threadIdx.x;
    if (i < e) {
        int s = ei[i];
        int d = ei[e + i];
        if ((unsigned)s >= (unsigned)n) s = 0;
        if ((unsigned)d >= (unsigned)n) d = 0;
        float norm = g_dis[s] * g_dis[d];
        int pos = atomicAdd(&g_cur[d], 1);
        g_csr[pos] = make_int2(s, __float_as_int(norm));
    }
}

// ---------------- operand prep ----------------
__global__ void split_x_kernel(const float* __restrict__ x, int M, int ntot) {
    int i = blockIdx.x * blockDim.x + threadIdx.x;
    if (i >= ntot) return;
    int row = i >> 7;
    float v = (row < M) ? x[i] : 0.0f;
    bsplit(v, g_ahi[i], g_alo[i]);
}
__global__ void split_w_kernel(const float* __restrict__ W, int slot, int colOff) {
    int i = blockIdx.x * blockDim.x + threadIdx.x;
    if (i >= HDIM * HDIM) return;
    int r = i >> 7, c = i & 127;
    size_t o = (size_t)slot * HDIM * 256 + (size_t)r * 256 + colOff + c;
    bsplit(W[i], g_whi[o], g_wlo[o]);
}

// ---------------- wmma bf16 3-term GEMM, smem-resident, double-buffered fill -------
// MODE 0 (pre): all cols -> g_hg raw
// MODE 1 (fused layer): cols 0-127 -> g_hg, cols 128-255 -> g_agg
#define LDA3 136
template <int NCOLS, int MODE>
__global__ __launch_bounds__(512, 1) void wmma_gemm(int slot) {
    extern __shared__ __nv_bfloat16 sm[];
    const int LDB3 = NCOLS + 8;
    const int ASZ = 128 * LDA3;
    const int BSZ = 128 * LDB3;
    __nv_bfloat16* Ah = sm;
    __nv_bfloat16* Al = sm + ASZ;
    __nv_bfloat16* Bh = sm + 2 * ASZ;
    __nv_bfloat16* Bl = sm + 2 * ASZ + BSZ;

    int tid = threadIdx.x;
    int warp = tid >> 5;
    int wm = warp & 3;                 // 4 row bands of 32
    int wn = warp >> 2;                // 4 col bands of NCOLS/4
    int block_row = blockIdx.x * 128;

    // Phase 0 fill: A cols 0-63 (K first half), B rows 0-63
    for (int idx = tid; idx < 128 * 8; idx += 512) {
        int r = idx >> 3;
        int c8 = (idx & 7) << 3;       // 0..56
        size_t go = (size_t)(block_row + r) * HDIM + c8;
        cp_async16(&Ah[r * LDA3 + c8], g_ahi + go);
        cp_async16(&Al[r * LDA3 + c8], g_alo + go);
    }
    for (int idx = tid; idx < 64 * (NCOLS / 8); idx += 512) {
        int r = idx / (NCOLS / 8);
        int c8 = (idx % (NCOLS / 8)) << 3;
        size_t go = (size_t)slot * HDIM * 256 + (size_t)r * 256 + c8;
        cp_async16(&Bh[r * LDB3 + c8], g_whi + go);
        cp_async16(&Bl[r * LDB3 + c8], g_wlo + go);
    }
    asm volatile("cp.async.commit_group;" ::: "memory");
    // Phase 1 fill: A cols 64-127, B rows 64-127
    for (int idx = tid; idx < 128 * 8; idx += 512) {
        int r = idx >> 3;
        int c8 = ((idx & 7) << 3) + 64;
        size_t go = (size_t)(block_row + r) * HDIM + c8;
        cp_async16(&Ah[r * LDA3 + c8], g_ahi + go);
        cp_async16(&Al[r * LDA3 + c8], g_alo + go);
    }
    for (int idx = tid; idx < 64 * (NCOLS / 8); idx += 512) {
        int r = 64 + idx / (NCOLS / 8);
        int c8 = (idx % (NCOLS / 8)) << 3;
        size_t go = (size_t)slot * HDIM * 256 + (size_t)r * 256 + c8;
        cp_async16(&Bh[r * LDB3 + c8], g_whi + go);
        cp_async16(&Bl[r * LDB3 + c8], g_wlo + go);
    }
    asm volatile("cp.async.commit_group;" ::: "memory");

    constexpr int NB = NCOLS / 64;
    wmma::fragment<wmma::accumulator, 16, 16, 16, float> acc[2][NB];
#pragma unroll
    for (int i = 0; i < 2; i++)
#pragma unroll
        for (int j = 0; j < NB; j++) wmma::fill_fragment(acc[i][j], 0.0f);

    int cbase = wn * (NCOLS / 4);

    // Consume phase 0 while phase 1 lands
    asm volatile("cp.async.wait_group 1;" ::: "memory");
    __syncthreads();
#pragma unroll
    for (int k = 0; k < 4; k++) {
        wmma::fragment<wmma::matrix_a, 16, 16, 16, __nv_bfloat16, wmma::row_major> ah[2], al[2];
        wmma::fragment<wmma::matrix_b, 16, 16, 16, __nv_bfloat16, wmma::row_major> bh[NB], bl[NB];
#pragma unroll
        for (int i = 0; i < 2; i++) {
            wmma::load_matrix_sync(ah[i], &Ah[(wm * 32 + i * 16) * LDA3 + k * 16], LDA3);
            wmma::load_matrix_sync(al[i], &Al[(wm * 32 + i * 16) * LDA3 + k * 16], LDA3);
        }
#pragma unroll
        for (int j = 0; j < NB; j++) {
            wmma::load_matrix_sync(bh[j], &Bh[(k * 16) * LDB3 + cbase + j * 16], LDB3);
            wmma::load_matrix_sync(bl[j], &Bl[(k * 16) * LDB3 + cbase + j * 16], LDB3);
        }
#pragma unroll
        for (int i = 0; i < 2; i++)
#pragma unroll
            for (int j = 0; j < NB; j++) {
                wmma::mma_sync(acc[i][j], ah[i], bh[j], acc[i][j]);
                wmma::mma_sync(acc[i][j], ah[i], bl[j], acc[i][j]);
                wmma::mma_sync(acc[i][j], al[i], bh[j], acc[i][j]);
            }
    }
    // Consume phase 1
    asm volatile("cp.async.wait_group 0;" ::: "memory");
    __syncthreads();
#pragma unroll
    for (int k = 4; k < 8; k++) {
        wmma::fragment<wmma::matrix_a, 16, 16, 16, __nv_bfloat16, wmma::row_major> ah[2], al[2];
        wmma::fragment<wmma::matrix_b, 16, 16, 16, __nv_bfloat16, wmma::row_major> bh[NB], bl[NB];
#pragma unroll
        for (int i = 0; i < 2; i++) {
            wmma::load_matrix_sync(ah[i], &Ah[(wm * 32 + i * 16) * LDA3 + k * 16], LDA3);
            wmma::load_matrix_sync(al[i], &Al[(wm * 32 + i * 16) * LDA3 + k * 16], LDA3);
        }
#pragma unroll
        for (int j = 0; j < NB; j++) {
            wmma::load_matrix_sync(bh[j], &Bh[(k * 16) * LDB3 + cbase + j * 16], LDB3);
            wmma::load_matrix_sync(bl[j], &Bl[(k * 16) * LDB3 + cbase + j * 16], LDB3);
        }
#pragma unroll
        for (int i = 0; i < 2; i++)
#pragma unroll
            for (int j = 0; j < NB; j++) {
                wmma::mma_sync(acc[i][j], ah[i], bh[j], acc[i][j]);
                wmma::mma_sync(acc[i][j], ah[i], bl[j], acc[i][j]);
                wmma::mma_sync(acc[i][j], al[i], bh[j], acc[i][j]);
            }
    }

#pragma unroll
    for (int i = 0; i < 2; i++)
#pragma unroll
        for (int j = 0; j < NB; j++) {
            int gr = block_row + wm * 32 + i * 16;
            int gc = cbase + j * 16;
            float* dst;
            if (MODE == 0 || gc < 128)
                dst = g_hg + (size_t)gr * HDIM + gc;
            else
                dst = g_agg + (size_t)gr * HDIM + (gc - 128);
            wmma::store_matrix_sync(dst, acc[i][j], HDIM, wmma::mem_row_major);
        }
}

// ---------------- pre activation: h = mish(t + b_pre); emit fp32 + bf16 split ----
__global__ void pre_act_kernel(const float* __restrict__ bias, int n4) {
    int i = blockIdx.x * blockDim.x + threadIdx.x;
    if (i >= n4) return;
    int c4 = i & 31;
    float4 t = reinterpret_cast<const float4*>(g_hg)[i];
    float4 b = reinterpret_cast<const float4*>(bias)[c4];
    float4 o;
    o.x = mishf(t.x + b.x);
    o.y = mishf(t.y + b.y);
    o.z = mishf(t.z + b.z);
    o.w = mishf(t.w + b.w);
    reinterpret_cast<float4*>(g_h)[i] = o;
    int e = i * 4;
    bsplit(o.x, g_ahi[e + 0], g_alo[e + 0]);
    bsplit(o.y, g_ahi[e + 1], g_alo[e + 1]);
    bsplit(o.z, g_ahi[e + 2], g_alo[e + 2]);
    bsplit(o.w, g_ahi[e + 3], g_alo[e + 3]);
}

// ---------------- CSR pull aggregation + biases + self-loop + mish + split ---------
__global__ __launch_bounds__(256) void csr_agg_kernel(const float* __restrict__ gb,
                                                      const float* __restrict__ sb) {
    int warp = (blockIdx.x * blockDim.x + threadIdx.x) >> 5;
    int lane = threadIdx.x & 31;
    if (warp >= NPAD) return;

    float4 acc = *reinterpret_cast<const float4*>(g_agg + (size_t)warp * HDIM + lane * 4);
    {
        float4 b1 = *reinterpret_cast<const float4*>(gb + lane * 4);
        float4 b2 = *reinterpret_cast<const float4*>(sb + lane * 4);
        float4 hv = *reinterpret_cast<const float4*>(g_hg + (size_t)warp * HDIM + lane * 4);
        float dis = g_dis[warp];
        float d2 = dis * dis;
        acc.x += b1.x + b2.x + d2 * hv.x;
        acc.y += b1.y + b2.y + d2 * hv.y;
        acc.z += b1.z + b2.z + d2 * hv.z;
        acc.w += b1.w + b2.w + d2 * hv.w;
    }
    int base = g_rowptr[warp];
    int end  = g_rowptr[warp + 1];

    int j = base;
    for (; j + 8 <= end; j += 8) {
        int2 e[8];
        float4 v[8];
#pragma unroll
        for (int q = 0; q < 8; q++) e[q] = __ldg(&g_csr[j + q]);
#pragma unroll
        for (int q = 0; q < 8; q++)
            v[q] = *reinterpret_cast<const float4*>(g_hg + (size_t)e[q].x * HDIM + lane * 4);
#pragma unroll
        for (int q = 0; q < 8; q++) {
            float n = __int_as_float(e[q].y);
            acc.x = fmaf(n, v[q].x, acc.x);
            acc.y = fmaf(n, v[q].y, acc.y);
            acc.z = fmaf(n, v[q].z, acc.z);
            acc.w = fmaf(n, v[q].w, acc.w);
        }
    }
    for (; j < end; j++) {
        int2 e = __ldg(&g_csr[j]);
        float4 v = *reinterpret_cast<const float4*>(g_hg + (size_t)e.x * HDIM + lane * 4);
        float n = __int_as_float(e.y);
        acc.x = fmaf(n, v.x, acc.x); acc.y = fmaf(n, v.y, acc.y);
        acc.z = fmaf(n, v.z, acc.z); acc.w = fmaf(n, v.w, acc.w);
    }

    float4 o;
    o.x = mishf(acc.x);
    o.y = mishf(acc.y);
    o.z = mishf(acc.z);
    o.w = mishf(acc.w);
    size_t fo = (size_t)warp * HDIM + lane * 4;
    *reinterpret_cast<float4*>(g_h + fo) = o;
    bsplit(o.x, g_ahi[fo + 0], g_alo[fo + 0]);
    bsplit(o.y, g_ahi[fo + 1], g_alo[fo + 1]);
    bsplit(o.z, g_ahi[fo + 2], g_alo[fo + 2]);
    bsplit(o.w, g_ahi[fo + 3], g_alo[fo + 3]);
}

// ---------------- post: out[i] = dot(h[i,:], W_post) + b_post ----------------
__global__ void post_kernel(const float* __restrict__ Wp,
                            const float* __restrict__ bp,
                            float* __restrict__ out, int M) {
    int warp = (blockIdx.x * blockDim.x + threadIdx.x) >> 5;
    int lane = threadIdx.x & 31;
    if (warp >= M) return;
    float4 hv = *reinterpret_cast<const float4*>(g_h + (size_t)warp * HDIM + lane * 4);
    float4 wv = *reinterpret_cast<const float4*>(Wp + lane * 4);
    float sum = hv.x * wv.x + hv.y * wv.y + hv.z * wv.z + hv.w * wv.w;
#pragma unroll
    for (int o = 16; o > 0; o >>= 1) sum += __shfl_xor_sync(0xFFFFFFFFu, sum, o);
    if (lane == 0) out[warp] = sum + bp[0];
}

// ---------------- launch ----------------
#define PRE_SMEM   ((2 * 128 * LDA3 + 2 * 128 * 136) * 2)
#define FUSED_SMEM ((2 * 128 * LDA3 + 2 * 128 * 264) * 2)

extern "C" void kernel_launch(void* const* d_in, const int* in_sizes, int n_in,
                              void* d_out, int out_size) {
    const float* x      = (const float*)d_in[0];
    const int*   ei     = (const int*)d_in[1];     // int32 (JAX x64-disabled)
    const float* W_pre  = (const float*)d_in[2];
    const float* b_pre  = (const float*)d_in[3];
    const float* gcn_W  = (const float*)d_in[4];
    const float* gcn_b  = (const float*)d_in[5];
    const float* skip_W = (const float*)d_in[6];
    const float* skip_b = (const float*)d_in[7];
    const float* W_post = (const float*)d_in[8];
    const float* b_post = (const float*)d_in[9];
    float*       out    = (float*)d_out;

    const int M = in_sizes[0] / HDIM;          // 50000
    const int E = in_sizes[1] / 2;             // 1600000
    const int L = in_sizes[4] / (HDIM * HDIM); // 3
    const int n4 = NPAD * (HDIM / 4);
    const int ntot = NPAD * HDIM;

    static cudaStream_t s1 = nullptr, s2 = nullptr;
    static cudaEvent_t evF1 = nullptr, evF2 = nullptr, evB = nullptr, evW = nullptr;
    if (!s1) {
        cudaStreamCreateWithFlags(&s1, cudaStreamNonBlocking);
        cudaStreamCreateWithFlags(&s2, cudaStreamNonBlocking);
        cudaEventCreateWithFlags(&evF1, cudaEventDisableTiming);
        cudaEventCreateWithFlags(&evF2, cudaEventDisableTiming);
        cudaEventCreateWithFlags(&evB, cudaEventDisableTiming);
        cudaEventCreateWithFlags(&evW, cudaEventDisableTiming);
        cudaFuncSetAttribute(wmma_gemm<128, 0>,
                             cudaFuncAttributeMaxDynamicSharedMemorySize, PRE_SMEM);
        cudaFuncSetAttribute(wmma_gemm<256, 1>,
                             cudaFuncAttributeMaxDynamicSharedMemorySize, FUSED_SMEM);
    }

    const int TB = 256;
    const int gemm_blocks = NPAD / 128;            // 392
    const int node_blocks = (NPAD + TB - 1) / TB;
    const int edge_blocks = (E + TB - 1) / TB;
    const int n4_blocks   = (n4 + TB - 1) / TB;
    const int nt_blocks   = (ntot + TB - 1) / TB;
    const int w_blocks    = (HDIM * HDIM + TB - 1) / TB;
    const int aggw_blocks = (NPAD * 32) / TB;
    const int post_blocks = (M * 32 + TB - 1) / TB;

    // ---- fork: CSR build on s1, layer-weight splits on s2 ----
    cudaEventRecord(evF1, 0);
    cudaStreamWaitEvent(s1, evF1, 0);
    cudaEventRecord(evF2, 0);
    cudaStreamWaitEvent(s2, evF2, 0);

    zero_cnt_kernel<<<node_blocks, TB, 0, s1>>>(NPAD);
    count_kernel<<<edge_blocks, TB, 0, s1>>>(ei, E, M);
    scan_kernel<<<1, 1024, 0, s1>>>();
    dis_kernel<<<node_blocks, TB, 0, s1>>>(NPAD);
    scatter_kernel<<<edge_blocks, TB, 0, s1>>>(ei, E, M);
    cudaEventRecord(evB, s1);

    for (int l = 0; l < L; l++) {
        split_w_kernel<<<w_blocks, TB, 0, s2>>>(gcn_W  + (size_t)l * HDIM * HDIM, 1 + l, 0);
        split_w_kernel<<<w_blocks, TB, 0, s2>>>(skip_W + (size_t)l * HDIM * HDIM, 1 + l, 128);
    }
    cudaEventRecord(evW, s2);

    // ---- main chain on stream 0 ----
    split_w_kernel<<<w_blocks, TB>>>(W_pre, 0, 0);
    split_x_kernel<<<nt_blocks, TB>>>(x, M, ntot);
    wmma_gemm<128, 0><<<gemm_blocks, 512, PRE_SMEM>>>(0);
    pre_act_kernel<<<n4_blocks, TB>>>(b_pre, n4);

    cudaStreamWaitEvent(0, evW, 0);    // layer weights ready
    for (int l = 0; l < L; l++) {
        const float* gb = gcn_b  + (size_t)l * HDIM;
        const float* sb = skip_b + (size_t)l * HDIM;
        wmma_gemm<256, 1><<<gemm_blocks, 512, FUSED_SMEM>>>(1 + l);
        if (l == 0) cudaStreamWaitEvent(0, evB, 0);   // CSR ready before first agg
        csr_agg_kernel<<<aggw_blocks, TB>>>(gb, sb);
    }

    post_kernel<<<post_blocks, TB>>>(W_post, b_post, out, M);
}

// round 14
// speedup vs baseline: 2.7213x; 1.0596x over previous
#include <cuda_runtime.h>
#include <cuda_bf16.h>
#include <cuda_fp16.h>
#include <math.h>
#include <mma.h>

using namespace nvcuda;

// Problem constants
#define NN    50000
#define NPAD  50176            // 392*128 full GEMM tiles; 1024*49 for the scan
#define EE    1600000
#define HDIM  128

// ---------------- static device scratch (allocation-free) ----------------
__device__ __align__(16) int   g_icnt[NPAD];
__device__ __align__(16) int   g_rowptr[NPAD + 1];
__device__ __align__(16) int   g_cur[NPAD];
__device__ __align__(16) int2  g_csr[EE];           // {src, norm-bits} grouped by dst
__device__ __align__(16) float g_dis[NPAD];
__device__ __align__(16) float g_h  [(size_t)NPAD * HDIM];
__device__ __align__(16) float g_hg [(size_t)NPAD * HDIM];   // fp32 hg (pre path only)
__device__ __align__(16) __half g_hg16[(size_t)NPAD * HDIM]; // fp16 hg (layer gather)
__device__ __align__(16) float g_agg[(size_t)NPAD * HDIM];
// bf16 hi/lo operand images
__device__ __align__(16) __nv_bfloat16 g_ahi[(size_t)NPAD * HDIM];
__device__ __align__(16) __nv_bfloat16 g_alo[(size_t)NPAD * HDIM];
// weight slots: slot 0 = W_pre (cols 0-127); slot 1+l = [gcn_W_l | skip_W_l] (256 cols)
__device__ __align__(16) __nv_bfloat16 g_whi[(size_t)4 * HDIM * 256];
__device__ __align__(16) __nv_bfloat16 g_wlo[(size_t)4 * HDIM * 256];

// ---------------- math helpers ----------------
__device__ __forceinline__ float mishf(float x) {
    float sp = fmaxf(x, 0.0f) + log1pf(expf(-fabsf(x)));
    return x * tanhf(sp);
}
__device__ __forceinline__ void bsplit(float x, __nv_bfloat16& h, __nv_bfloat16& l) {
    h = __float2bfloat16_rn(x);
    l = __float2bfloat16_rn(x - __bfloat162float(h));
}
__device__ __forceinline__ void cp_async16(void* smem_dst, const void* gmem_src) {
    unsigned s = (unsigned)__cvta_generic_to_shared(smem_dst);
    asm volatile("cp.async.ca.shared.global [%0], [%1], 16;" :: "r"(s), "l"(gmem_src) : "memory");
}

// ---------------- CSR build ----------------
__global__ void zero_cnt_kernel(int n) {
    int i = blockIdx.x * blockDim.x + threadIdx.x;
    if (i < n) g_icnt[i] = 0;
}
__global__ void count_kernel(const int* __restrict__ ei, int e, int n) {
    int i = blockIdx.x * blockDim.x + threadIdx.x;
    if (i < e) {
        int d = ei[e + i];
        if ((unsigned)d >= (unsigned)n) d = 0;
        atomicAdd(&g_icnt[d], 1);
    }
}
__global__ void scan_kernel() {
    __shared__ int part[1024];
    const int CH = NPAD / 1024;            // 49
    int t = threadIdx.x;
    int base = t * CH;
    int sum = 0;
    for (int i = 0; i < CH; i++) sum += g_icnt[base + i];
    part[t] = sum;
    __syncthreads();
    for (int off = 1; off < 1024; off <<= 1) {
        int v = (t >= off) ? part[t - off] : 0;
        __syncthreads();
        part[t] += v;
        __syncthreads();
    }
    int run = part[t] - sum;
    for (int i = 0; i < CH; i++) {
        int c = g_icnt[base + i];
        g_rowptr[base + i] = run;
        g_cur[base + i]    = run;
        run += c;
    }
    if (t == 1023) g_rowptr[NPAD] = run;
}
__global__ void dis_kernel(int n) {
    int i = blockIdx.x * blockDim.x + threadIdx.x;
    if (i < n) g_dis[i] = rsqrtf(1.0f + (float)g_icnt[i]);
}
__global__ void scatter_kernel(const int* __restrict__ ei, int e, int n) {
    int i = blockIdx.x * blockDim.x + threadIdx.x;
    if (i < e) {
        int s = ei[i];
        int d = ei[e + i];
        if ((unsigned)s >= (unsigned)n) s = 0;
        if ((unsigned)d >= (unsigned)n) d = 0;
        float norm = g_dis[s] * g_dis[d];
        int pos = atomicAdd(&g_cur[d], 1);
        g_csr[pos] = make_int2(s, __float_as_int(norm));
    }
}

// ---------------- operand prep ----------------
__global__ void split_x_kernel(const float* __restrict__ x, int M, int ntot) {
    int i = blockIdx.x * blockDim.x + threadIdx.x;
    if (i >= ntot) return;
    int row = i >> 7;
    float v = (row < M) ? x[i] : 0.0f;
    bsplit(v, g_ahi[i], g_alo[i]);
}
__global__ void split_w_kernel(const float* __restrict__ W, int slot, int colOff) {
    int i = blockIdx.x * blockDim.x + threadIdx.x;
    if (i >= HDIM * HDIM) return;
    int r = i >> 7, c = i & 127;
    size_t o = (size_t)slot * HDIM * 256 + (size_t)r * 256 + colOff + c;
    bsplit(W[i], g_whi[o], g_wlo[o]);
}

// ---------------- wmma bf16 3-term GEMM, smem-resident, double-buffered fill -------
// MODE 0 (pre): all cols -> g_hg fp32
// MODE 1 (fused layer): cols 0-127 -> g_hg16 (fp16, via smem staging),
//                       cols 128-255 -> g_agg fp32
#define LDA3 136
template <int NCOLS, int MODE>
__global__ __launch_bounds__(512, 1) void wmma_gemm(int slot) {
    extern __shared__ __nv_bfloat16 sm[];
    const int LDB3 = NCOLS + 8;
    const int ASZ = 128 * LDA3;
    const int BSZ = 128 * LDB3;
    __nv_bfloat16* Ah = sm;
    __nv_bfloat16* Al = sm + ASZ;
    __nv_bfloat16* Bh = sm + 2 * ASZ;
    __nv_bfloat16* Bl = sm + 2 * ASZ + BSZ;
    // MODE 1 epilogue reuses [Ah|Al] as a 128x132 fp32 staging buffer:
    static_assert(128 * 132 * 4 <= 2 * 128 * LDA3 * 2, "fp32 staging must fit in Ah+Al");

    int tid = threadIdx.x;
    int warp = tid >> 5;
    int wm = warp & 3;                 // 4 row bands of 32
    int wn = warp >> 2;                // 4 col bands of NCOLS/4
    int block_row = blockIdx.x * 128;

    // Phase 0 fill: A cols 0-63, B rows 0-63
    for (int idx = tid; idx < 128 * 8; idx += 512) {
        int r = idx >> 3;
        int c8 = (idx & 7) << 3;
        size_t go = (size_t)(block_row + r) * HDIM + c8;
        cp_async16(&Ah[r * LDA3 + c8], g_ahi + go);
        cp_async16(&Al[r * LDA3 + c8], g_alo + go);
    }
    for (int idx = tid; idx < 64 * (NCOLS / 8); idx += 512) {
        int r = idx / (NCOLS / 8);
        int c8 = (idx % (NCOLS / 8)) << 3;
        size_t go = (size_t)slot * HDIM * 256 + (size_t)r * 256 + c8;
        cp_async16(&Bh[r * LDB3 + c8], g_whi + go);
        cp_async16(&Bl[r * LDB3 + c8], g_wlo + go);
    }
    asm volatile("cp.async.commit_group;" ::: "memory");
    // Phase 1 fill: A cols 64-127, B rows 64-127
    for (int idx = tid; idx < 128 * 8; idx += 512) {
        int r = idx >> 3;
        int c8 = ((idx & 7) << 3) + 64;
        size_t go = (size_t)(block_row + r) * HDIM + c8;
        cp_async16(&Ah[r * LDA3 + c8], g_ahi + go);
        cp_async16(&Al[r * LDA3 + c8], g_alo + go);
    }
    for (int idx = tid; idx < 64 * (NCOLS / 8); idx += 512) {
        int r = 64 + idx / (NCOLS / 8);
        int c8 = (idx % (NCOLS / 8)) << 3;
        size_t go = (size_t)slot * HDIM * 256 + (size_t)r * 256 + c8;
        cp_async16(&Bh[r * LDB3 + c8], g_whi + go);
        cp_async16(&Bl[r * LDB3 + c8], g_wlo + go);
    }
    asm volatile("cp.async.commit_group;" ::: "memory");

    constexpr int NB = NCOLS / 64;
    wmma::fragment<wmma::accumulator, 16, 16, 16, float> acc[2][NB];
#pragma unroll
    for (int i = 0; i < 2; i++)
#pragma unroll
        for (int j = 0; j < NB; j++) wmma::fill_fragment(acc[i][j], 0.0f);

    int cbase = wn * (NCOLS / 4);

    asm volatile("cp.async.wait_group 1;" ::: "memory");
    __syncthreads();
#pragma unroll
    for (int k = 0; k < 4; k++) {
        wmma::fragment<wmma::matrix_a, 16, 16, 16, __nv_bfloat16, wmma::row_major> ah[2], al[2];
        wmma::fragment<wmma::matrix_b, 16, 16, 16, __nv_bfloat16, wmma::row_major> bh[NB], bl[NB];
#pragma unroll
        for (int i = 0; i < 2; i++) {
            wmma::load_matrix_sync(ah[i], &Ah[(wm * 32 + i * 16) * LDA3 + k * 16], LDA3);
            wmma::load_matrix_sync(al[i], &Al[(wm * 32 + i * 16) * LDA3 + k * 16], LDA3);
        }
#pragma unroll
        for (int j = 0; j < NB; j++) {
            wmma::load_matrix_sync(bh[j], &Bh[(k * 16) * LDB3 + cbase + j * 16], LDB3);
            wmma::load_matrix_sync(bl[j], &Bl[(k * 16) * LDB3 + cbase + j * 16], LDB3);
        }
#pragma unroll
        for (int i = 0; i < 2; i++)
#pragma unroll
            for (int j = 0; j < NB; j++) {
                wmma::mma_sync(acc[i][j], ah[i], bh[j], acc[i][j]);
                wmma::mma_sync(acc[i][j], ah[i], bl[j], acc[i][j]);
                wmma::mma_sync(acc[i][j], al[i], bh[j], acc[i][j]);
            }
    }
    asm volatile("cp.async.wait_group 0;" ::: "memory");
    __syncthreads();
#pragma unroll
    for (int k = 4; k < 8; k++) {
        wmma::fragment<wmma::matrix_a, 16, 16, 16, __nv_bfloat16, wmma::row_major> ah[2], al[2];
        wmma::fragment<wmma::matrix_b, 16, 16, 16, __nv_bfloat16, wmma::row_major> bh[NB], bl[NB];
#pragma unroll
        for (int i = 0; i < 2; i++) {
            wmma::load_matrix_sync(ah[i], &Ah[(wm * 32 + i * 16) * LDA3 + k * 16], LDA3);
            wmma::load_matrix_sync(al[i], &Al[(wm * 32 + i * 16) * LDA3 + k * 16], LDA3);
        }
#pragma unroll
        for (int j = 0; j < NB; j++) {
            wmma::load_matrix_sync(bh[j], &Bh[(k * 16) * LDB3 + cbase + j * 16], LDB3);
            wmma::load_matrix_sync(bl[j], &Bl[(k * 16) * LDB3 + cbase + j * 16], LDB3);
        }
#pragma unroll
        for (int i = 0; i < 2; i++)
#pragma unroll
            for (int j = 0; j < NB; j++) {
                wmma::mma_sync(acc[i][j], ah[i], bh[j], acc[i][j]);
                wmma::mma_sync(acc[i][j], ah[i], bl[j], acc[i][j]);
                wmma::mma_sync(acc[i][j], al[i], bh[j], acc[i][j]);
            }
    }

    if (MODE == 0) {
#pragma unroll
        for (int i = 0; i < 2; i++)
#pragma unroll
            for (int j = 0; j < NB; j++)
                wmma::store_matrix_sync(
                    g_hg + (size_t)(block_row + wm * 32 + i * 16) * HDIM + cbase + j * 16,
                    acc[i][j], HDIM, wmma::mem_row_major);
    } else {
        // gcn half -> smem staging -> fp16 global; skip half -> fp32 g_agg
        float* Sf = reinterpret_cast<float*>(sm);   // 128 x 132 fp32 staged in Ah|Al
        __syncthreads();                            // mainloop smem reads complete
#pragma unroll
        for (int i = 0; i < 2; i++)
#pragma unroll
            for (int j = 0; j < NB; j++) {
                int lr = wm * 32 + i * 16;
                int gc = cbase + j * 16;
                if (gc < 128)
                    wmma::store_matrix_sync(&Sf[lr * 132 + gc], acc[i][j], 132, wmma::mem_row_major);
                else
                    wmma::store_matrix_sync(
                        g_agg + (size_t)(block_row + lr) * HDIM + (gc - 128),
                        acc[i][j], HDIM, wmma::mem_row_major);
            }
        __syncthreads();
        for (int idx = tid; idx < 128 * 16; idx += 512) {
            int r = idx >> 4;
            int c8 = (idx & 15) << 3;
            float4 v0 = *reinterpret_cast<float4*>(&Sf[r * 132 + c8]);
            float4 v1 = *reinterpret_cast<float4*>(&Sf[r * 132 + c8 + 4]);
            __half2 hh[4];
            hh[0] = __floats2half2_rn(v0.x, v0.y);
            hh[1] = __floats2half2_rn(v0.z, v0.w);
            hh[2] = __floats2half2_rn(v1.x, v1.y);
            hh[3] = __floats2half2_rn(v1.z, v1.w);
            *reinterpret_cast<uint4*>(g_hg16 + (size_t)(block_row + r) * HDIM + c8) =
                *reinterpret_cast<uint4*>(hh);
        }
    }
}

// ---------------- pre activation: h = mish(t + b_pre); emit fp32 + bf16 split ----
__global__ void pre_act_kernel(const float* __restrict__ bias, int n4) {
    int i = blockIdx.x * blockDim.x + threadIdx.x;
    if (i >= n4) return;
    int c4 = i & 31;
    float4 t = reinterpret_cast<const float4*>(g_hg)[i];
    float4 b = reinterpret_cast<const float4*>(bias)[c4];
    float4 o;
    o.x = mishf(t.x + b.x);
    o.y = mishf(t.y + b.y);
    o.z = mishf(t.z + b.z);
    o.w = mishf(t.w + b.w);
    reinterpret_cast<float4*>(g_h)[i] = o;
    int e = i * 4;
    bsplit(o.x, g_ahi[e + 0], g_alo[e + 0]);
    bsplit(o.y, g_ahi[e + 1], g_alo[e + 1]);
    bsplit(o.z, g_ahi[e + 2], g_alo[e + 2]);
    bsplit(o.w, g_ahi[e + 3], g_alo[e + 3]);
}

// ---------------- CSR pull aggregation (fp16 gather) + biases + self-loop + mish ---
__global__ __launch_bounds__(256) void csr_agg_kernel(const float* __restrict__ gb,
                                                      const float* __restrict__ sb) {
    int warp = (blockIdx.x * blockDim.x + threadIdx.x) >> 5;
    int lane = threadIdx.x & 31;
    if (warp >= NPAD) return;

    float4 acc = *reinterpret_cast<const float4*>(g_agg + (size_t)warp * HDIM + lane * 4);
    {
        float4 b1 = *reinterpret_cast<const float4*>(gb + lane * 4);
        float4 b2 = *reinterpret_cast<const float4*>(sb + lane * 4);
        uint2 u = *reinterpret_cast<const uint2*>(g_hg16 + (size_t)warp * HDIM + lane * 4);
        float2 f0 = __half22float2(*reinterpret_cast<__half2*>(&u.x));
        float2 f1 = __half22float2(*reinterpret_cast<__half2*>(&u.y));
        float dis = g_dis[warp];
        float d2 = dis * dis;
        acc.x += b1.x + b2.x + d2 * f0.x;
        acc.y += b1.y + b2.y + d2 * f0.y;
        acc.z += b1.z + b2.z + d2 * f1.x;
        acc.w += b1.w + b2.w + d2 * f1.y;
    }
    int base = g_rowptr[warp];
    int end  = g_rowptr[warp + 1];

    int j = base;
    for (; j + 8 <= end; j += 8) {
        int2 e[8];
        uint2 u[8];
#pragma unroll
        for (int q = 0; q < 8; q++) e[q] = __ldg(&g_csr[j + q]);
#pragma unroll
        for (int q = 0; q < 8; q++)
            u[q] = __ldg(reinterpret_cast<const uint2*>(
                       g_hg16 + (size_t)e[q].x * HDIM + lane * 4));
#pragma unroll
        for (int q = 0; q < 8; q++) {
            float n = __int_as_float(e[q].y);
            float2 f0 = __half22float2(*reinterpret_cast<__half2*>(&u[q].x));
            float2 f1 = __half22float2(*reinterpret_cast<__half2*>(&u[q].y));
            acc.x = fmaf(n, f0.x, acc.x);
            acc.y = fmaf(n, f0.y, acc.y);
            acc.z = fmaf(n, f1.x, acc.z);
            acc.w = fmaf(n, f1.y, acc.w);
        }
    }
    for (; j < end; j++) {
        int2 e = __ldg(&g_csr[j]);
        uint2 u = __ldg(reinterpret_cast<const uint2*>(
                      g_hg16 + (size_t)e.x * HDIM + lane * 4));
        float n = __int_as_float(e.y);
        float2 f0 = __half22float2(*reinterpret_cast<__half2*>(&u.x));
        float2 f1 = __half22float2(*reinterpret_cast<__half2*>(&u.y));
        acc.x = fmaf(n, f0.x, acc.x);
        acc.y = fmaf(n, f0.y, acc.y);
        acc.z = fmaf(n, f1.x, acc.z);
        acc.w = fmaf(n, f1.y, acc.w);
    }

    float4 o;
    o.x = mishf(acc.x);
    o.y = mishf(acc.y);
    o.z = mishf(acc.z);
    o.w = mishf(acc.w);
    size_t fo = (size_t)warp * HDIM + lane * 4;
    *reinterpret_cast<float4*>(g_h + fo) = o;
    bsplit(o.x, g_ahi[fo + 0], g_alo[fo + 0]);
    bsplit(o.y, g_ahi[fo + 1], g_alo[fo + 1]);
    bsplit(o.z, g_ahi[fo + 2], g_alo[fo + 2]);
    bsplit(o.w, g_ahi[fo + 3], g_alo[fo + 3]);
}

// ---------------- post: out[i] = dot(h[i,:], W_post) + b_post ----------------
__global__ void post_kernel(const float* __restrict__ Wp,
                            const float* __restrict__ bp,
                            float* __restrict__ out, int M) {
    int warp = (blockIdx.x * blockDim.x + threadIdx.x) >> 5;
    int lane = threadIdx.x & 31;
    if (warp >= M) return;
    float4 hv = *reinterpret_cast<const float4*>(g_h + (size_t)warp * HDIM + lane * 4);
    float4 wv = *reinterpret_cast<const float4*>(Wp + lane * 4);
    float sum = hv.x * wv.x + hv.y * wv.y + hv.z * wv.z + hv.w * wv.w;
#pragma unroll
    for (int o = 16; o > 0; o >>= 1) sum += __shfl_xor_sync(0xFFFFFFFFu, sum, o);
    if (lane == 0) out[warp] = sum + bp[0];
}

// ---------------- launch ----------------
#define PRE_SMEM   ((2 * 128 * LDA3 + 2 * 128 * 136) * 2)
#define FUSED_SMEM ((2 * 128 * LDA3 + 2 * 128 * 264) * 2)

extern "C" void kernel_launch(void* const* d_in, const int* in_sizes, int n_in,
                              void* d_out, int out_size) {
    const float* x      = (const float*)d_in[0];
    const int*   ei     = (const int*)d_in[1];     // int32 (JAX x64-disabled)
    const float* W_pre  = (const float*)d_in[2];
    const float* b_pre  = (const float*)d_in[3];
    const float* gcn_W  = (const float*)d_in[4];
    const float* gcn_b  = (const float*)d_in[5];
    const float* skip_W = (const float*)d_in[6];
    const float* skip_b = (const float*)d_in[7];
    const float* W_post = (const float*)d_in[8];
    const float* b_post = (const float*)d_in[9];
    float*       out    = (float*)d_out;

    const int M = in_sizes[0] / HDIM;          // 50000
    const int E = in_sizes[1] / 2;             // 1600000
    const int L = in_sizes[4] / (HDIM * HDIM); // 3
    const int n4 = NPAD * (HDIM / 4);
    const int ntot = NPAD * HDIM;

    static cudaStream_t s1 = nullptr, s2 = nullptr;
    static cudaEvent_t evF1 = nullptr, evF2 = nullptr, evB = nullptr, evW = nullptr;
    if (!s1) {
        cudaStreamCreateWithFlags(&s1, cudaStreamNonBlocking);
        cudaStreamCreateWithFlags(&s2, cudaStreamNonBlocking);
        cudaEventCreateWithFlags(&evF1, cudaEventDisableTiming);
        cudaEventCreateWithFlags(&evF2, cudaEventDisableTiming);
        cudaEventCreateWithFlags(&evB, cudaEventDisableTiming);
        cudaEventCreateWithFlags(&evW, cudaEventDisableTiming);
        cudaFuncSetAttribute(wmma_gemm<128, 0>,
                             cudaFuncAttributeMaxDynamicSharedMemorySize, PRE_SMEM);
        cudaFuncSetAttribute(wmma_gemm<256, 1>,
                             cudaFuncAttributeMaxDynamicSharedMemorySize, FUSED_SMEM);
    }

    const int TB = 256;
    const int gemm_blocks = NPAD / 128;            // 392
    const int node_blocks = (NPAD + TB - 1) / TB;
    const int edge_blocks = (E + TB - 1) / TB;
    const int n4_blocks   = (n4 + TB - 1) / TB;
    const int nt_blocks   = (ntot + TB - 1) / TB;
    const int w_blocks    = (HDIM * HDIM + TB - 1) / TB;
    const int aggw_blocks = (NPAD * 32) / TB;
    const int post_blocks = (M * 32 + TB - 1) / TB;

    // ---- fork: CSR build on s1, layer-weight splits on s2 ----
    cudaEventRecord(evF1, 0);
    cudaStreamWaitEvent(s1, evF1, 0);
    cudaEventRecord(evF2, 0);
    cudaStreamWaitEvent(s2, evF2, 0);

    zero_cnt_kernel<<<node_blocks, TB, 0, s1>>>(NPAD);
    count_kernel<<<edge_blocks, TB, 0, s1>>>(ei, E, M);
    scan_kernel<<<1, 1024, 0, s1>>>();
    dis_kernel<<<node_blocks, TB, 0, s1>>>(NPAD);
    scatter_kernel<<<edge_blocks, TB, 0, s1>>>(ei, E, M);
    cudaEventRecord(evB, s1);

    for (int l = 0; l < L; l++) {
        split_w_kernel<<<w_blocks, TB, 0, s2>>>(gcn_W  + (size_t)l * HDIM * HDIM, 1 + l, 0);
        split_w_kernel<<<w_blocks, TB, 0, s2>>>(skip_W + (size_t)l * HDIM * HDIM, 1 + l, 128);
    }
    cudaEventRecord(evW, s2);

    // ---- main chain on stream 0 ----
    split_w_kernel<<<w_blocks, TB>>>(W_pre, 0, 0);
    split_x_kernel<<<nt_blocks, TB>>>(x, M, ntot);
    wmma_gemm<128, 0><<<gemm_blocks, 512, PRE_SMEM>>>(0);
    pre_act_kernel<<<n4_blocks, TB>>>(b_pre, n4);

    cudaStreamWaitEvent(0, evW, 0);    // layer weights ready
    for (int l = 0; l < L; l++) {
        const float* gb = gcn_b  + (size_t)l * HDIM;
        const float* sb = skip_b + (size_t)l * HDIM;
        wmma_gemm<256, 1><<<gemm_blocks, 512, FUSED_SMEM>>>(1 + l);
        if (l == 0) cudaStreamWaitEvent(0, evB, 0);   // CSR ready before first agg
        csr_agg_kernel<<<aggw_blocks, TB>>>(gb, sb);
    }

    post_kernel<<<post_blocks, TB>>>(W_post, b_post, out, M);
}

// round 15
// speedup vs baseline: 2.9244x; 1.0746x over previous
#include <cuda_runtime.h>
#include <cuda_bf16.h>
#include <cuda_fp16.h>
#include <math.h>
#include <mma.h>

using namespace nvcuda;

// Problem constants
#define NN    50000
#define NPAD  50176            // 392*128 full GEMM tiles; 1024*49 for the scan
#define EE    1600000
#define HDIM  128

// ---------------- static device scratch (allocation-free) ----------------
__device__ __align__(16) int   g_icnt[NPAD];
__device__ __align__(16) int   g_rowptr[NPAD + 1];
__device__ __align__(16) int   g_cur[NPAD];
__device__ __align__(16) int2  g_csr[EE];           // {src, norm-bits} grouped by dst
__device__ __align__(16) float g_dis[NPAD];
__device__ __align__(16) float g_hg [(size_t)NPAD * HDIM];   // fp32 hg (pre path only)
__device__ __align__(16) __half g_hg16[(size_t)NPAD * HDIM]; // fp16 hg (layer gather)
__device__ __align__(16) float g_agg[(size_t)NPAD * HDIM];
// bf16 hi/lo operand images
__device__ __align__(16) __nv_bfloat16 g_ahi[(size_t)NPAD * HDIM];
__device__ __align__(16) __nv_bfloat16 g_alo[(size_t)NPAD * HDIM];
// weight slots: slot 0 = W_pre (cols 0-127); slot 1+l = [gcn_W_l | skip_W_l] (256 cols)
__device__ __align__(16) __nv_bfloat16 g_whi[(size_t)4 * HDIM * 256];
__device__ __align__(16) __nv_bfloat16 g_wlo[(size_t)4 * HDIM * 256];

// ---------------- math helpers ----------------
__device__ __forceinline__ float mishf(float x) {
    float sp = fmaxf(x, 0.0f) + log1pf(expf(-fabsf(x)));
    return x * tanhf(sp);
}
__device__ __forceinline__ void bsplit(float x, __nv_bfloat16& h, __nv_bfloat16& l) {
    h = __float2bfloat16_rn(x);
    l = __float2bfloat16_rn(x - __bfloat162float(h));
}
__device__ __forceinline__ void cp_async16(void* smem_dst, const void* gmem_src) {
    unsigned s = (unsigned)__cvta_generic_to_shared(smem_dst);
    asm volatile("cp.async.ca.shared.global [%0], [%1], 16;" :: "r"(s), "l"(gmem_src) : "memory");
}

// ---------------- CSR build ----------------
__global__ void zero_cnt_kernel(int n) {
    int i = blockIdx.x * blockDim.x + threadIdx.x;
    if (i < n) g_icnt[i] = 0;
}
__global__ void count_kernel(const int* __restrict__ ei, int e, int n) {
    int i = blockIdx.x * blockDim.x + threadIdx.x;
    if (i < e) {
        int d = ei[e + i];
        if ((unsigned)d >= (unsigned)n) d = 0;
        atomicAdd(&g_icnt[d], 1);
    }
}
__global__ void scan_kernel() {
    __shared__ int part[1024];
    const int CH = NPAD / 1024;            // 49
    int t = threadIdx.x;
    int base = t * CH;
    int sum = 0;
    for (int i = 0; i < CH; i++) sum += g_icnt[base + i];
    part[t] = sum;
    __syncthreads();
    for (int off = 1; off < 1024; off <<= 1) {
        int v = (t >= off) ? part[t - off] : 0;
        __syncthreads();
        part[t] += v;
        __syncthreads();
    }
    int run = part[t] - sum;
    for (int i = 0; i < CH; i++) {
        int c = g_icnt[base + i];
        g_rowptr[base + i] = run;
        g_cur[base + i]    = run;
        run += c;
    }
    if (t == 1023) g_rowptr[NPAD] = run;
}
__global__ void dis_kernel(int n) {
    int i = blockIdx.x * blockDim.x + threadIdx.x;
    if (i < n) g_dis[i] = rsqrtf(1.0f + (float)g_icnt[i]);
}
__global__ void scatter_kernel(const int* __restrict__ ei, int e, int n) {
    int i = blockIdx.x * blockDim.x + threadIdx.x;
    if (i < e) {
        int s = ei[i];
        int d = ei[e + i];
        if ((unsigned)s >= (unsigned)n) s = 0;
        if ((unsigned)d >= (unsigned)n) d = 0;
        float norm = g_dis[s] * g_dis[d];
        int pos = atomicAdd(&g_cur[d], 1);
        g_csr[pos] = make_int2(s, __float_as_int(norm));
    }
}

// ---------------- operand prep ----------------
__global__ void split_x_kernel(const float* __restrict__ x, int M, int ntot) {
    int i = blockIdx.x * blockDim.x + threadIdx.x;
    if (i >= ntot) return;
    int row = i >> 7;
    float v = (row < M) ? x[i] : 0.0f;
    bsplit(v, g_ahi[i], g_alo[i]);
}
__global__ void split_w_kernel(const float* __restrict__ W, int slot, int colOff) {
    int i = blockIdx.x * blockDim.x + threadIdx.x;
    if (i >= HDIM * HDIM) return;
    int r = i >> 7, c = i & 127;
    size_t o = (size_t)slot * HDIM * 256 + (size_t)r * 256 + colOff + c;
    bsplit(W[i], g_whi[o], g_wlo[o]);
}

// ---------------- wmma bf16 3-term GEMM, smem-resident, double-buffered fill -------
// MODE 0 (pre): all cols -> g_hg fp32
// MODE 1 (fused layer): cols 0-127 -> g_hg16 (fp16, via smem staging),
//                       cols 128-255 -> g_agg fp32
#define LDA3 136
template <int NCOLS, int MODE>
__global__ __launch_bounds__(512, 1) void wmma_gemm(int slot) {
    extern __shared__ __nv_bfloat16 sm[];
    const int LDB3 = NCOLS + 8;
    const int ASZ = 128 * LDA3;
    const int BSZ = 128 * LDB3;
    __nv_bfloat16* Ah = sm;
    __nv_bfloat16* Al = sm + ASZ;
    __nv_bfloat16* Bh = sm + 2 * ASZ;
    __nv_bfloat16* Bl = sm + 2 * ASZ + BSZ;
    // MODE 1 epilogue reuses [Ah|Al] as a 128x132 fp32 staging buffer:
    static_assert(128 * 132 * 4 <= 2 * 128 * LDA3 * 2, "fp32 staging must fit in Ah+Al");

    int tid = threadIdx.x;
    int warp = tid >> 5;
    int wm = warp & 3;                 // 4 row bands of 32
    int wn = warp >> 2;                // 4 col bands of NCOLS/4
    int block_row = blockIdx.x * 128;

    // Phase 0 fill: A cols 0-63, B rows 0-63
    for (int idx = tid; idx < 128 * 8; idx += 512) {
        int r = idx >> 3;
        int c8 = (idx & 7) << 3;
        size_t go = (size_t)(block_row + r) * HDIM + c8;
        cp_async16(&Ah[r * LDA3 + c8], g_ahi + go);
        cp_async16(&Al[r * LDA3 + c8], g_alo + go);
    }
    for (int idx = tid; idx < 64 * (NCOLS / 8); idx += 512) {
        int r = idx / (NCOLS / 8);
        int c8 = (idx % (NCOLS / 8)) << 3;
        size_t go = (size_t)slot * HDIM * 256 + (size_t)r * 256 + c8;
        cp_async16(&Bh[r * LDB3 + c8], g_whi + go);
        cp_async16(&Bl[r * LDB3 + c8], g_wlo + go);
    }
    asm volatile("cp.async.commit_group;" ::: "memory");
    // Phase 1 fill: A cols 64-127, B rows 64-127
    for (int idx = tid; idx < 128 * 8; idx += 512) {
        int r = idx >> 3;
        int c8 = ((idx & 7) << 3) + 64;
        size_t go = (size_t)(block_row + r) * HDIM + c8;
        cp_async16(&Ah[r * LDA3 + c8], g_ahi + go);
        cp_async16(&Al[r * LDA3 + c8], g_alo + go);
    }
    for (int idx = tid; idx < 64 * (NCOLS / 8); idx += 512) {
        int r = 64 + idx / (NCOLS / 8);
        int c8 = (idx % (NCOLS / 8)) << 3;
        size_t go = (size_t)slot * HDIM * 256 + (size_t)r * 256 + c8;
        cp_async16(&Bh[r * LDB3 + c8], g_whi + go);
        cp_async16(&Bl[r * LDB3 + c8], g_wlo + go);
    }
    asm volatile("cp.async.commit_group;" ::: "memory");

    constexpr int NB = NCOLS / 64;
    wmma::fragment<wmma::accumulator, 16, 16, 16, float> acc[2][NB];
#pragma unroll
    for (int i = 0; i < 2; i++)
#pragma unroll
        for (int j = 0; j < NB; j++) wmma::fill_fragment(acc[i][j], 0.0f);

    int cbase = wn * (NCOLS / 4);

    asm volatile("cp.async.wait_group 1;" ::: "memory");
    __syncthreads();
#pragma unroll
    for (int k = 0; k < 4; k++) {
        wmma::fragment<wmma::matrix_a, 16, 16, 16, __nv_bfloat16, wmma::row_major> ah[2], al[2];
        wmma::fragment<wmma::matrix_b, 16, 16, 16, __nv_bfloat16, wmma::row_major> bh[NB], bl[NB];
#pragma unroll
        for (int i = 0; i < 2; i++) {
            wmma::load_matrix_sync(ah[i], &Ah[(wm * 32 + i * 16) * LDA3 + k * 16], LDA3);
            wmma::load_matrix_sync(al[i], &Al[(wm * 32 + i * 16) * LDA3 + k * 16], LDA3);
        }
#pragma unroll
        for (int j = 0; j < NB; j++) {
            wmma::load_matrix_sync(bh[j], &Bh[(k * 16) * LDB3 + cbase + j * 16], LDB3);
            wmma::load_matrix_sync(bl[j], &Bl[(k * 16) * LDB3 + cbase + j * 16], LDB3);
        }
#pragma unroll
        for (int i = 0; i < 2; i++)
#pragma unroll
            for (int j = 0; j < NB; j++) {
                wmma::mma_sync(acc[i][j], ah[i], bh[j], acc[i][j]);
                wmma::mma_sync(acc[i][j], ah[i], bl[j], acc[i][j]);
                wmma::mma_sync(acc[i][j], al[i], bh[j], acc[i][j]);
            }
    }
    asm volatile("cp.async.wait_group 0;" ::: "memory");
    __syncthreads();
#pragma unroll
    for (int k = 4; k < 8; k++) {
        wmma::fragment<wmma::matrix_a, 16, 16, 16, __nv_bfloat16, wmma::row_major> ah[2], al[2];
        wmma::fragment<wmma::matrix_b, 16, 16, 16, __nv_bfloat16, wmma::row_major> bh[NB], bl[NB];
#pragma unroll
        for (int i = 0; i < 2; i++) {
            wmma::load_matrix_sync(ah[i], &Ah[(wm * 32 + i * 16) * LDA3 + k * 16], LDA3);
            wmma::load_matrix_sync(al[i], &Al[(wm * 32 + i * 16) * LDA3 + k * 16], LDA3);
        }
#pragma unroll
        for (int j = 0; j < NB; j++) {
            wmma::load_matrix_sync(bh[j], &Bh[(k * 16) * LDB3 + cbase + j * 16], LDB3);
            wmma::load_matrix_sync(bl[j], &Bl[(k * 16) * LDB3 + cbase + j * 16], LDB3);
        }
#pragma unroll
        for (int i = 0; i < 2; i++)
#pragma unroll
            for (int j = 0; j < NB; j++) {
                wmma::mma_sync(acc[i][j], ah[i], bh[j], acc[i][j]);
                wmma::mma_sync(acc[i][j], ah[i], bl[j], acc[i][j]);
                wmma::mma_sync(acc[i][j], al[i], bh[j], acc[i][j]);
            }
    }

    if (MODE == 0) {
#pragma unroll
        for (int i = 0; i < 2; i++)
#pragma unroll
            for (int j = 0; j < NB; j++)
                wmma::store_matrix_sync(
                    g_hg + (size_t)(block_row + wm * 32 + i * 16) * HDIM + cbase + j * 16,
                    acc[i][j], HDIM, wmma::mem_row_major);
    } else {
        // gcn half -> smem staging -> fp16 global; skip half -> fp32 g_agg
        float* Sf = reinterpret_cast<float*>(sm);   // 128 x 132 fp32 staged in Ah|Al
        __syncthreads();                            // mainloop smem reads complete
#pragma unroll
        for (int i = 0; i < 2; i++)
#pragma unroll
            for (int j = 0; j < NB; j++) {
                int lr = wm * 32 + i * 16;
                int gc = cbase + j * 16;
                if (gc < 128)
                    wmma::store_matrix_sync(&Sf[lr * 132 + gc], acc[i][j], 132, wmma::mem_row_major);
                else
                    wmma::store_matrix_sync(
                        g_agg + (size_t)(block_row + lr) * HDIM + (gc - 128),
                        acc[i][j], HDIM, wmma::mem_row_major);
            }
        __syncthreads();
        for (int idx = tid; idx < 128 * 16; idx += 512) {
            int r = idx >> 4;
            int c8 = (idx & 15) << 3;
            float4 v0 = *reinterpret_cast<float4*>(&Sf[r * 132 + c8]);
            float4 v1 = *reinterpret_cast<float4*>(&Sf[r * 132 + c8 + 4]);
            __half2 hh[4];
            hh[0] = __floats2half2_rn(v0.x, v0.y);
            hh[1] = __floats2half2_rn(v0.z, v0.w);
            hh[2] = __floats2half2_rn(v1.x, v1.y);
            hh[3] = __floats2half2_rn(v1.z, v1.w);
            *reinterpret_cast<uint4*>(g_hg16 + (size_t)(block_row + r) * HDIM + c8) =
                *reinterpret_cast<uint4*>(hh);
        }
    }
}

// ---------------- pre activation: h = mish(t + b_pre); emit bf16 split only ----
__global__ void pre_act_kernel(const float* __restrict__ bias, int n4) {
    int i = blockIdx.x * blockDim.x + threadIdx.x;
    if (i >= n4) return;
    int c4 = i & 31;
    float4 t = reinterpret_cast<const float4*>(g_hg)[i];
    float4 b = reinterpret_cast<const float4*>(bias)[c4];
    float4 o;
    o.x = mishf(t.x + b.x);
    o.y = mishf(t.y + b.y);
    o.z = mishf(t.z + b.z);
    o.w = mishf(t.w + b.w);
    int e = i * 4;
    bsplit(o.x, g_ahi[e + 0], g_alo[e + 0]);
    bsplit(o.y, g_ahi[e + 1], g_alo[e + 1]);
    bsplit(o.z, g_ahi[e + 2], g_alo[e + 2]);
    bsplit(o.w, g_ahi[e + 3], g_alo[e + 3]);
}

// ---------------- CSR pull aggregation (fp16 gather) + biases + self-loop + mish ---
// LAST=false: h -> bf16 hi/lo splits (next layer's A operand)
// LAST=true:  fused postprocess: out[v] = dot(h[v], W_post) + b_post; no stores else
template <bool LAST>
__global__ __launch_bounds__(256) void csr_agg_kernel(const float* __restrict__ gb,
                                                      const float* __restrict__ sb,
                                                      const float* __restrict__ Wp,
                                                      const float* __restrict__ bp,
                                                      float* __restrict__ out, int M) {
    int warp = (blockIdx.x * blockDim.x + threadIdx.x) >> 5;
    int lane = threadIdx.x & 31;
    if (warp >= NPAD) return;
    if (LAST && warp >= M) return;     // padded rows produce no output

    float4 acc = *reinterpret_cast<const float4*>(g_agg + (size_t)warp * HDIM + lane * 4);
    {
        float4 b1 = *reinterpret_cast<const float4*>(gb + lane * 4);
        float4 b2 = *reinterpret_cast<const float4*>(sb + lane * 4);
        uint2 u = *reinterpret_cast<const uint2*>(g_hg16 + (size_t)warp * HDIM + lane * 4);
        float2 f0 = __half22float2(*reinterpret_cast<__half2*>(&u.x));
        float2 f1 = __half22float2(*reinterpret_cast<__half2*>(&u.y));
        float dis = g_dis[warp];
        float d2 = dis * dis;
        acc.x += b1.x + b2.x + d2 * f0.x;
        acc.y += b1.y + b2.y + d2 * f0.y;
        acc.z += b1.z + b2.z + d2 * f1.x;
        acc.w += b1.w + b2.w + d2 * f1.y;
    }
    int base = g_rowptr[warp];
    int end  = g_rowptr[warp + 1];

    int j = base;
    for (; j + 8 <= end; j += 8) {
        int2 e[8];
        uint2 u[8];
#pragma unroll
        for (int q = 0; q < 8; q++) e[q] = __ldg(&g_csr[j + q]);
#pragma unroll
        for (int q = 0; q < 8; q++)
            u[q] = __ldg(reinterpret_cast<const uint2*>(
                       g_hg16 + (size_t)e[q].x * HDIM + lane * 4));
#pragma unroll
        for (int q = 0; q < 8; q++) {
            float n = __int_as_float(e[q].y);
            float2 f0 = __half22float2(*reinterpret_cast<__half2*>(&u[q].x));
            float2 f1 = __half22float2(*reinterpret_cast<__half2*>(&u[q].y));
            acc.x = fmaf(n, f0.x, acc.x);
            acc.y = fmaf(n, f0.y, acc.y);
            acc.z = fmaf(n, f1.x, acc.z);
            acc.w = fmaf(n, f1.y, acc.w);
        }
    }
    for (; j < end; j++) {
        int2 e = __ldg(&g_csr[j]);
        uint2 u = __ldg(reinterpret_cast<const uint2*>(
                      g_hg16 + (size_t)e.x * HDIM + lane * 4));
        float n = __int_as_float(e.y);
        float2 f0 = __half22float2(*reinterpret_cast<__half2*>(&u.x));
        float2 f1 = __half22float2(*reinterpret_cast<__half2*>(&u.y));
        acc.x = fmaf(n, f0.x, acc.x);
        acc.y = fmaf(n, f0.y, acc.y);
        acc.z = fmaf(n, f1.x, acc.z);
        acc.w = fmaf(n, f1.y, acc.w);
    }

    float4 o;
    o.x = mishf(acc.x);
    o.y = mishf(acc.y);
    o.z = mishf(acc.z);
    o.w = mishf(acc.w);

    if (LAST) {
        float4 wv = *reinterpret_cast<const float4*>(Wp + lane * 4);
        float sum = o.x * wv.x + o.y * wv.y + o.z * wv.z + o.w * wv.w;
#pragma unroll
        for (int s = 16; s > 0; s >>= 1) sum += __shfl_xor_sync(0xFFFFFFFFu, sum, s);
        if (lane == 0) out[warp] = sum + bp[0];
    } else {
        size_t fo = (size_t)warp * HDIM + lane * 4;
        bsplit(o.x, g_ahi[fo + 0], g_alo[fo + 0]);
        bsplit(o.y, g_ahi[fo + 1], g_alo[fo + 1]);
        bsplit(o.z, g_ahi[fo + 2], g_alo[fo + 2]);
        bsplit(o.w, g_ahi[fo + 3], g_alo[fo + 3]);
    }
}

// ---------------- launch ----------------
#define PRE_SMEM   ((2 * 128 * LDA3 + 2 * 128 * 136) * 2)
#define FUSED_SMEM ((2 * 128 * LDA3 + 2 * 128 * 264) * 2)

extern "C" void kernel_launch(void* const* d_in, const int* in_sizes, int n_in,
                              void* d_out, int out_size) {
    const float* x      = (const float*)d_in[0];
    const int*   ei     = (const int*)d_in[1];     // int32 (JAX x64-disabled)
    const float* W_pre  = (const float*)d_in[2];
    const float* b_pre  = (const float*)d_in[3];
    const float* gcn_W  = (const float*)d_in[4];
    const float* gcn_b  = (const float*)d_in[5];
    const float* skip_W = (const float*)d_in[6];
    const float* skip_b = (const float*)d_in[7];
    const float* W_post = (const float*)d_in[8];
    const float* b_post = (const float*)d_in[9];
    float*       out    = (float*)d_out;

    const int M = in_sizes[0] / HDIM;          // 50000
    const int E = in_sizes[1] / 2;             // 1600000
    const int L = in_sizes[4] / (HDIM * HDIM); // 3
    const int n4 = NPAD * (HDIM / 4);
    const int ntot = NPAD * HDIM;

    static cudaStream_t s1 = nullptr, s2 = nullptr;
    static cudaEvent_t evF1 = nullptr, evF2 = nullptr, evB = nullptr, evW = nullptr;
    if (!s1) {
        cudaStreamCreateWithFlags(&s1, cudaStreamNonBlocking);
        cudaStreamCreateWithFlags(&s2, cudaStreamNonBlocking);
        cudaEventCreateWithFlags(&evF1, cudaEventDisableTiming);
        cudaEventCreateWithFlags(&evF2, cudaEventDisableTiming);
        cudaEventCreateWithFlags(&evB, cudaEventDisableTiming);
        cudaEventCreateWithFlags(&evW, cudaEventDisableTiming);
        cudaFuncSetAttribute(wmma_gemm<128, 0>,
                             cudaFuncAttributeMaxDynamicSharedMemorySize, PRE_SMEM);
        cudaFuncSetAttribute(wmma_gemm<256, 1>,
                             cudaFuncAttributeMaxDynamicSharedMemorySize, FUSED_SMEM);
    }

    const int TB = 256;
    const int gemm_blocks = NPAD / 128;            // 392
    const int node_blocks = (NPAD + TB - 1) / TB;
    const int edge_blocks = (E + TB - 1) / TB;
    const int n4_blocks   = (n4 + TB - 1) / TB;
    const int nt_blocks   = (ntot + TB - 1) / TB;
    const int w_blocks    = (HDIM * HDIM + TB - 1) / TB;
    const int aggw_blocks = (NPAD * 32) / TB;
    const int post_blocks = (M * 32 + TB - 1) / TB;

    // ---- fork: CSR build on s1, layer-weight splits on s2 ----
    cudaEventRecord(evF1, 0);
    cudaStreamWaitEvent(s1, evF1, 0);
    cudaEventRecord(evF2, 0);
    cudaStreamWaitEvent(s2, evF2, 0);

    zero_cnt_kernel<<<node_blocks, TB, 0, s1>>>(NPAD);
    count_kernel<<<edge_blocks, TB, 0, s1>>>(ei, E, M);
    scan_kernel<<<1, 1024, 0, s1>>>();
    dis_kernel<<<node_blocks, TB, 0, s1>>>(NPAD);
    scatter_kernel<<<edge_blocks, TB, 0, s1>>>(ei, E, M);
    cudaEventRecord(evB, s1);

    for (int l = 0; l < L; l++) {
        split_w_kernel<<<w_blocks, TB, 0, s2>>>(gcn_W  + (size_t)l * HDIM * HDIM, 1 + l, 0);
        split_w_kernel<<<w_blocks, TB, 0, s2>>>(skip_W + (size_t)l * HDIM * HDIM, 1 + l, 128);
    }
    cudaEventRecord(evW, s2);

    // ---- main chain on stream 0 ----
    split_w_kernel<<<w_blocks, TB>>>(W_pre, 0, 0);
    split_x_kernel<<<nt_blocks, TB>>>(x, M, ntot);
    wmma_gemm<128, 0><<<gemm_blocks, 512, PRE_SMEM>>>(0);
    pre_act_kernel<<<n4_blocks, TB>>>(b_pre, n4);

    cudaStreamWaitEvent(0, evW, 0);    // layer weights ready
    for (int l = 0; l < L; l++) {
        const float* gb = gcn_b  + (size_t)l * HDIM;
        const float* sb = skip_b + (size_t)l * HDIM;
        wmma_gemm<256, 1><<<gemm_blocks, 512, FUSED_SMEM>>>(1 + l);
        if (l == 0) cudaStreamWaitEvent(0, evB, 0);   // CSR ready before first agg
        if (l == L - 1)
            csr_agg_kernel<true><<<post_blocks, TB>>>(gb, sb, W_post, b_post, out, M);
        else
            csr_agg_kernel<false><<<aggw_blocks, TB>>>(gb, sb, nullptr, nullptr, nullptr, M);
    }
}

// round 16
// speedup vs baseline: 3.0938x; 1.0579x over previous
#include <cuda_runtime.h>
#include <cuda_bf16.h>
#include <cuda_fp16.h>
#include <math.h>
#include <mma.h>

using namespace nvcuda;

// Problem constants
#define NN    50000
#define NPAD  50176            // 392*128 full GEMM tiles; 1024*49 for the scan
#define EE    1600000
#define HDIM  128

// ---------------- static device scratch (allocation-free) ----------------
__device__ __align__(16) int   g_icnt[NPAD];
__device__ __align__(16) int   g_rowptr[NPAD + 1];
__device__ __align__(16) int   g_cur[NPAD];
__device__ __align__(16) int2  g_csr[EE];           // {src, norm-bits} grouped by dst
__device__ __align__(16) float g_dis[NPAD];
__device__ __align__(16) __half g_hg16[(size_t)NPAD * HDIM]; // fp16 hg (layer gather)
__device__ __align__(16) float g_agg[(size_t)NPAD * HDIM];
// bf16 hi/lo operand images
__device__ __align__(16) __nv_bfloat16 g_ahi[(size_t)NPAD * HDIM];
__device__ __align__(16) __nv_bfloat16 g_alo[(size_t)NPAD * HDIM];
// weight slots: slot 0 = W_pre (cols 0-127); slot 1+l = [gcn_W_l | skip_W_l] (256 cols)
__device__ __align__(16) __nv_bfloat16 g_whi[(size_t)4 * HDIM * 256];
__device__ __align__(16) __nv_bfloat16 g_wlo[(size_t)4 * HDIM * 256];

// ---------------- math helpers ----------------
__device__ __forceinline__ float mishf(float x) {
    float sp = fmaxf(x, 0.0f) + log1pf(expf(-fabsf(x)));
    return x * tanhf(sp);
}
__device__ __forceinline__ void bsplit(float x, __nv_bfloat16& h, __nv_bfloat16& l) {
    h = __float2bfloat16_rn(x);
    l = __float2bfloat16_rn(x - __bfloat162float(h));
}
__device__ __forceinline__ void cp_async16(void* smem_dst, const void* gmem_src) {
    unsigned s = (unsigned)__cvta_generic_to_shared(smem_dst);
    asm volatile("cp.async.ca.shared.global [%0], [%1], 16;" :: "r"(s), "l"(gmem_src) : "memory");
}

// ---------------- CSR build ----------------
__global__ void zero_cnt_kernel(int n) {
    int i = blockIdx.x * blockDim.x + threadIdx.x;
    if (i < n) g_icnt[i] = 0;
}
__global__ void count_kernel(const int* __restrict__ ei, int e, int n) {
    int i = blockIdx.x * blockDim.x + threadIdx.x;
    if (i < e) {
        int d = ei[e + i];
        if ((unsigned)d >= (unsigned)n) d = 0;
        atomicAdd(&g_icnt[d], 1);
    }
}
__global__ void scan_kernel() {
    __shared__ int part[1024];
    const int CH = NPAD / 1024;            // 49
    int t = threadIdx.x;
    int base = t * CH;
    int sum = 0;
    for (int i = 0; i < CH; i++) sum += g_icnt[base + i];
    part[t] = sum;
    __syncthreads();
    for (int off = 1; off < 1024; off <<= 1) {
        int v = (t >= off) ? part[t - off] : 0;
        __syncthreads();
        part[t] += v;
        __syncthreads();
    }
    int run = part[t] - sum;
    for (int i = 0; i < CH; i++) {
        int c = g_icnt[base + i];
        g_rowptr[base + i] = run;
        g_cur[base + i]    = run;
        run += c;
    }
    if (t == 1023) g_rowptr[NPAD] = run;
}
__global__ void dis_kernel(int n) {
    int i = blockIdx.x * blockDim.x + threadIdx.x;
    if (i < n) g_dis[i] = rsqrtf(1.0f + (float)g_icnt[i]);
}
__global__ void scatter_kernel(const int* __restrict__ ei, int e, int n) {
    int i = blockIdx.x * blockDim.x + threadIdx.x;
    if (i < e) {
        int s = ei[i];
        int d = ei[e + i];
        if ((unsigned)s >= (unsigned)n) s = 0;
        if ((unsigned)d >= (unsigned)n) d = 0;
        float norm = g_dis[s] * g_dis[d];
        int pos = atomicAdd(&g_cur[d], 1);
        g_csr[pos] = make_int2(s, __float_as_int(norm));
    }
}

// ---------------- operand prep ----------------
__global__ void split_x_kernel(const float* __restrict__ x, int M, int ntot) {
    int i = blockIdx.x * blockDim.x + threadIdx.x;
    if (i >= ntot) return;
    int row = i >> 7;
    float v = (row < M) ? x[i] : 0.0f;
    bsplit(v, g_ahi[i], g_alo[i]);
}
__global__ void split_w_kernel(const float* __restrict__ W, int slot, int colOff) {
    int i = blockIdx.x * blockDim.x + threadIdx.x;
    if (i >= HDIM * HDIM) return;
    int r = i >> 7, c = i & 127;
    size_t o = (size_t)slot * HDIM * 256 + (size_t)r * 256 + colOff + c;
    bsplit(W[i], g_whi[o], g_wlo[o]);
}

// ---------------- wmma bf16 3-term GEMM, smem-resident, double-buffered fill -------
// MODE 0 (pre):  fused epilogue: h = mish(acc + b_pre) -> g_ahi/g_alo bf16 splits
// MODE 1 (layer): cols 0-127 -> g_hg16 (fp16, via smem staging),
//                 cols 128-255 -> g_agg fp32
#define LDA3 136
template <int NCOLS, int MODE>
__global__ __launch_bounds__(512, 1) void wmma_gemm(int slot, const float* __restrict__ bias) {
    extern __shared__ __nv_bfloat16 sm[];
    const int LDB3 = NCOLS + 8;
    const int ASZ = 128 * LDA3;
    const int BSZ = 128 * LDB3;
    __nv_bfloat16* Ah = sm;
    __nv_bfloat16* Al = sm + ASZ;
    __nv_bfloat16* Bh = sm + 2 * ASZ;
    __nv_bfloat16* Bl = sm + 2 * ASZ + BSZ;
    // Epilogues reuse [Ah|Al] as a 128x132 fp32 staging buffer:
    static_assert(128 * 132 * 4 <= 2 * 128 * LDA3 * 2, "fp32 staging must fit in Ah+Al");

    int tid = threadIdx.x;
    int warp = tid >> 5;
    int wm = warp & 3;                 // 4 row bands of 32
    int wn = warp >> 2;                // 4 col bands of NCOLS/4
    int block_row = blockIdx.x * 128;

    // Phase 0 fill: A cols 0-63, B rows 0-63
    for (int idx = tid; idx < 128 * 8; idx += 512) {
        int r = idx >> 3;
        int c8 = (idx & 7) << 3;
        size_t go = (size_t)(block_row + r) * HDIM + c8;
        cp_async16(&Ah[r * LDA3 + c8], g_ahi + go);
        cp_async16(&Al[r * LDA3 + c8], g_alo + go);
    }
    for (int idx = tid; idx < 64 * (NCOLS / 8); idx += 512) {
        int r = idx / (NCOLS / 8);
        int c8 = (idx % (NCOLS / 8)) << 3;
        size_t go = (size_t)slot * HDIM * 256 + (size_t)r * 256 + c8;
        cp_async16(&Bh[r * LDB3 + c8], g_whi + go);
        cp_async16(&Bl[r * LDB3 + c8], g_wlo + go);
    }
    asm volatile("cp.async.commit_group;" ::: "memory");
    // Phase 1 fill: A cols 64-127, B rows 64-127
    for (int idx = tid; idx < 128 * 8; idx += 512) {
        int r = idx >> 3;
        int c8 = ((idx & 7) << 3) + 64;
        size_t go = (size_t)(block_row + r) * HDIM + c8;
        cp_async16(&Ah[r * LDA3 + c8], g_ahi + go);
        cp_async16(&Al[r * LDA3 + c8], g_alo + go);
    }
    for (int idx = tid; idx < 64 * (NCOLS / 8); idx += 512) {
        int r = 64 + idx / (NCOLS / 8);
        int c8 = (idx % (NCOLS / 8)) << 3;
        size_t go = (size_t)slot * HDIM * 256 + (size_t)r * 256 + c8;
        cp_async16(&Bh[r * LDB3 + c8], g_whi + go);
        cp_async16(&Bl[r * LDB3 + c8], g_wlo + go);
    }
    asm volatile("cp.async.commit_group;" ::: "memory");

    constexpr int NB = NCOLS / 64;
    wmma::fragment<wmma::accumulator, 16, 16, 16, float> acc[2][NB];
#pragma unroll
    for (int i = 0; i < 2; i++)
#pragma unroll
        for (int j = 0; j < NB; j++) wmma::fill_fragment(acc[i][j], 0.0f);

    int cbase = wn * (NCOLS / 4);

    asm volatile("cp.async.wait_group 1;" ::: "memory");
    __syncthreads();
#pragma unroll
    for (int k = 0; k < 4; k++) {
        wmma::fragment<wmma::matrix_a, 16, 16, 16, __nv_bfloat16, wmma::row_major> ah[2], al[2];
        wmma::fragment<wmma::matrix_b, 16, 16, 16, __nv_bfloat16, wmma::row_major> bh[NB], bl[NB];
#pragma unroll
        for (int i = 0; i < 2; i++) {
            wmma::load_matrix_sync(ah[i], &Ah[(wm * 32 + i * 16) * LDA3 + k * 16], LDA3);
            wmma::load_matrix_sync(al[i], &Al[(wm * 32 + i * 16) * LDA3 + k * 16], LDA3);
        }
#pragma unroll
        for (int j = 0; j < NB; j++) {
            wmma::load_matrix_sync(bh[j], &Bh[(k * 16) * LDB3 + cbase + j * 16], LDB3);
            wmma::load_matrix_sync(bl[j], &Bl[(k * 16) * LDB3 + cbase + j * 16], LDB3);
        }
#pragma unroll
        for (int i = 0; i < 2; i++)
#pragma unroll
            for (int j = 0; j < NB; j++) {
                wmma::mma_sync(acc[i][j], ah[i], bh[j], acc[i][j]);
                wmma::mma_sync(acc[i][j], ah[i], bl[j], acc[i][j]);
                wmma::mma_sync(acc[i][j], al[i], bh[j], acc[i][j]);
            }
    }
    asm volatile("cp.async.wait_group 0;" ::: "memory");
    __syncthreads();
#pragma unroll
    for (int k = 4; k < 8; k++) {
        wmma::fragment<wmma::matrix_a, 16, 16, 16, __nv_bfloat16, wmma::row_major> ah[2], al[2];
        wmma::fragment<wmma::matrix_b, 16, 16, 16, __nv_bfloat16, wmma::row_major> bh[NB], bl[NB];
#pragma unroll
        for (int i = 0; i < 2; i++) {
            wmma::load_matrix_sync(ah[i], &Ah[(wm * 32 + i * 16) * LDA3 + k * 16], LDA3);
            wmma::load_matrix_sync(al[i], &Al[(wm * 32 + i * 16) * LDA3 + k * 16], LDA3);
        }
#pragma unroll
        for (int j = 0; j < NB; j++) {
            wmma::load_matrix_sync(bh[j], &Bh[(k * 16) * LDB3 + cbase + j * 16], LDB3);
            wmma::load_matrix_sync(bl[j], &Bl[(k * 16) * LDB3 + cbase + j * 16], LDB3);
        }
#pragma unroll
        for (int i = 0; i < 2; i++)
#pragma unroll
            for (int j = 0; j < NB; j++) {
                wmma::mma_sync(acc[i][j], ah[i], bh[j], acc[i][j]);
                wmma::mma_sync(acc[i][j], ah[i], bl[j], acc[i][j]);
                wmma::mma_sync(acc[i][j], al[i], bh[j], acc[i][j]);
            }
    }

    float* Sf = reinterpret_cast<float*>(sm);   // 128 x 132 fp32 staged in Ah|Al
    if (MODE == 0) {
        // Fused preprocess epilogue: stage fp32, then mish(acc + b_pre) -> bf16 splits
        __syncthreads();
#pragma unroll
        for (int i = 0; i < 2; i++)
#pragma unroll
            for (int j = 0; j < NB; j++)
                wmma::store_matrix_sync(&Sf[(wm * 32 + i * 16) * 132 + cbase + j * 16],
                                        acc[i][j], 132, wmma::mem_row_major);
        __syncthreads();
        for (int idx = tid; idx < 128 * 32; idx += 512) {
            int r = idx >> 5;
            int c4 = (idx & 31) << 2;
            float4 t = *reinterpret_cast<float4*>(&Sf[r * 132 + c4]);
            float4 b = *reinterpret_cast<const float4*>(bias + c4);
            size_t fo = (size_t)(block_row + r) * HDIM + c4;
            float o0 = mishf(t.x + b.x), o1 = mishf(t.y + b.y);
            float o2 = mishf(t.z + b.z), o3 = mishf(t.w + b.w);
            __nv_bfloat16 h4[4], l4[4];
            bsplit(o0, h4[0], l4[0]);
            bsplit(o1, h4[1], l4[1]);
            bsplit(o2, h4[2], l4[2]);
            bsplit(o3, h4[3], l4[3]);
            *reinterpret_cast<uint2*>(g_ahi + fo) = *reinterpret_cast<uint2*>(h4);
            *reinterpret_cast<uint2*>(g_alo + fo) = *reinterpret_cast<uint2*>(l4);
        }
    } else {
        // gcn half -> smem staging -> fp16 global; skip half -> fp32 g_agg
        __syncthreads();                            // mainloop smem reads complete
#pragma unroll
        for (int i = 0; i < 2; i++)
#pragma unroll
            for (int j = 0; j < NB; j++) {
                int lr = wm * 32 + i * 16;
                int gc = cbase + j * 16;
                if (gc < 128)
                    wmma::store_matrix_sync(&Sf[lr * 132 + gc], acc[i][j], 132, wmma::mem_row_major);
                else
                    wmma::store_matrix_sync(
                        g_agg + (size_t)(block_row + lr) * HDIM + (gc - 128),
                        acc[i][j], HDIM, wmma::mem_row_major);
            }
        __syncthreads();
        for (int idx = tid; idx < 128 * 16; idx += 512) {
            int r = idx >> 4;
            int c8 = (idx & 15) << 3;
            float4 v0 = *reinterpret_cast<float4*>(&Sf[r * 132 + c8]);
            float4 v1 = *reinterpret_cast<float4*>(&Sf[r * 132 + c8 + 4]);
            __half2 hh[4];
            hh[0] = __floats2half2_rn(v0.x, v0.y);
            hh[1] = __floats2half2_rn(v0.z, v0.w);
            hh[2] = __floats2half2_rn(v1.x, v1.y);
            hh[3] = __floats2half2_rn(v1.z, v1.w);
            *reinterpret_cast<uint4*>(g_hg16 + (size_t)(block_row + r) * HDIM + c8) =
                *reinterpret_cast<uint4*>(hh);
        }
    }
}

// ---------------- CSR pull aggregation (fp16 gather) + biases + self-loop + mish ---
// LAST=false: h -> bf16 hi/lo splits (next layer's A operand)
// LAST=true:  fused postprocess: out[v] = dot(h[v], W_post) + b_post
template <bool LAST>
__global__ __launch_bounds__(256) void csr_agg_kernel(const float* __restrict__ gb,
                                                      const float* __restrict__ sb,
                                                      const float* __restrict__ Wp,
                                                      const float* __restrict__ bp,
                                                      float* __restrict__ out, int M) {
    int warp = (blockIdx.x * blockDim.x + threadIdx.x) >> 5;
    int lane = threadIdx.x & 31;
    if (warp >= NPAD) return;
    if (LAST && warp >= M) return;     // padded rows produce no output

    float4 acc = *reinterpret_cast<const float4*>(g_agg + (size_t)warp * HDIM + lane * 4);
    {
        float4 b1 = *reinterpret_cast<const float4*>(gb + lane * 4);
        float4 b2 = *reinterpret_cast<const float4*>(sb + lane * 4);
        uint2 u = *reinterpret_cast<const uint2*>(g_hg16 + (size_t)warp * HDIM + lane * 4);
        float2 f0 = __half22float2(*reinterpret_cast<__half2*>(&u.x));
        float2 f1 = __half22float2(*reinterpret_cast<__half2*>(&u.y));
        float dis = g_dis[warp];
        float d2 = dis * dis;
        acc.x += b1.x + b2.x + d2 * f0.x;
        acc.y += b1.y + b2.y + d2 * f0.y;
        acc.z += b1.z + b2.z + d2 * f1.x;
        acc.w += b1.w + b2.w + d2 * f1.y;
    }
    int base = g_rowptr[warp];
    int end  = g_rowptr[warp + 1];

    int j = base;
    for (; j + 8 <= end; j += 8) {
        int2 e[8];
        uint2 u[8];
#pragma unroll
        for (int q = 0; q < 8; q++) e[q] = __ldg(&g_csr[j + q]);
#pragma unroll
        for (int q = 0; q < 8; q++)
            u[q] = __ldg(reinterpret_cast<const uint2*>(
                       g_hg16 + (size_t)e[q].x * HDIM + lane * 4));
#pragma unroll
        for (int q = 0; q < 8; q++) {
            float n = __int_as_float(e[q].y);
            float2 f0 = __half22float2(*reinterpret_cast<__half2*>(&u[q].x));
            float2 f1 = __half22float2(*reinterpret_cast<__half2*>(&u[q].y));
            acc.x = fmaf(n, f0.x, acc.x);
            acc.y = fmaf(n, f0.y, acc.y);
            acc.z = fmaf(n, f1.x, acc.z);
            acc.w = fmaf(n, f1.y, acc.w);
        }
    }
    for (; j < end; j++) {
        int2 e = __ldg(&g_csr[j]);
        uint2 u = __ldg(reinterpret_cast<const uint2*>(
                      g_hg16 + (size_t)e.x * HDIM + lane * 4));
        float n = __int_as_float(e.y);
        float2 f0 = __half22float2(*reinterpret_cast<__half2*>(&u.x));
        float2 f1 = __half22float2(*reinterpret_cast<__half2*>(&u.y));
        acc.x = fmaf(n, f0.x, acc.x);
        acc.y = fmaf(n, f0.y, acc.y);
        acc.z = fmaf(n, f1.x, acc.z);
        acc.w = fmaf(n, f1.y, acc.w);
    }

    float4 o;
    o.x = mishf(acc.x);
    o.y = mishf(acc.y);
    o.z = mishf(acc.z);
    o.w = mishf(acc.w);

    if (LAST) {
        float4 wv = *reinterpret_cast<const float4*>(Wp + lane * 4);
        float sum = o.x * wv.x + o.y * wv.y + o.z * wv.z + o.w * wv.w;
#pragma unroll
        for (int s = 16; s > 0; s >>= 1) sum += __shfl_xor_sync(0xFFFFFFFFu, sum, s);
        if (lane == 0) out[warp] = sum + bp[0];
    } else {
        size_t fo = (size_t)warp * HDIM + lane * 4;
        bsplit(o.x, g_ahi[fo + 0], g_alo[fo + 0]);
        bsplit(o.y, g_ahi[fo + 1], g_alo[fo + 1]);
        bsplit(o.z, g_ahi[fo + 2], g_alo[fo + 2]);
        bsplit(o.w, g_ahi[fo + 3], g_alo[fo + 3]);
    }
}

// ---------------- launch ----------------
#define PRE_SMEM   ((2 * 128 * LDA3 + 2 * 128 * 136) * 2)
#define FUSED_SMEM ((2 * 128 * LDA3 + 2 * 128 * 264) * 2)

extern "C" void kernel_launch(void* const* d_in, const int* in_sizes, int n_in,
                              void* d_out, int out_size) {
    const float* x      = (const float*)d_in[0];
    const int*   ei     = (const int*)d_in[1];     // int32 (JAX x64-disabled)
    const float* W_pre  = (const float*)d_in[2];
    const float* b_pre  = (const float*)d_in[3];
    const float* gcn_W  = (const float*)d_in[4];
    const float* gcn_b  = (const float*)d_in[5];
    const float* skip_W = (const float*)d_in[6];
    const float* skip_b = (const float*)d_in[7];
    const float* W_post = (const float*)d_in[8];
    const float* b_post = (const float*)d_in[9];
    float*       out    = (float*)d_out;

    const int M = in_sizes[0] / HDIM;          // 50000
    const int E = in_sizes[1] / 2;             // 1600000
    const int L = in_sizes[4] / (HDIM * HDIM); // 3
    const int ntot = NPAD * HDIM;

    static cudaStream_t s1 = nullptr, s2 = nullptr;
    static cudaEvent_t evF1 = nullptr, evF2 = nullptr, evB = nullptr, evW = nullptr;
    if (!s1) {
        cudaStreamCreateWithFlags(&s1, cudaStreamNonBlocking);
        cudaStreamCreateWithFlags(&s2, cudaStreamNonBlocking);
        cudaEventCreateWithFlags(&evF1, cudaEventDisableTiming);
        cudaEventCreateWithFlags(&evF2, cudaEventDisableTiming);
        cudaEventCreateWithFlags(&evB, cudaEventDisableTiming);
        cudaEventCreateWithFlags(&evW, cudaEventDisableTiming);
        cudaFuncSetAttribute(wmma_gemm<128, 0>,
                             cudaFuncAttributeMaxDynamicSharedMemorySize, PRE_SMEM);
        cudaFuncSetAttribute(wmma_gemm<256, 1>,
                             cudaFuncAttributeMaxDynamicSharedMemorySize, FUSED_SMEM);
    }

    const int TB = 256;
    const int gemm_blocks = NPAD / 128;            // 392
    const int node_blocks = (NPAD + TB - 1) / TB;
    const int edge_blocks = (E + TB - 1) / TB;
    const int nt_blocks   = (ntot + TB - 1) / TB;
    const int w_blocks    = (HDIM * HDIM + TB - 1) / TB;
    const int aggw_blocks = (NPAD * 32) / TB;
    const int post_blocks = (M * 32 + TB - 1) / TB;

    // ---- fork: CSR build on s1, layer-weight splits on s2 ----
    cudaEventRecord(evF1, 0);
    cudaStreamWaitEvent(s1, evF1, 0);
    cudaEventRecord(evF2, 0);
    cudaStreamWaitEvent(s2, evF2, 0);

    zero_cnt_kernel<<<node_blocks, TB, 0, s1>>>(NPAD);
    count_kernel<<<edge_blocks, TB, 0, s1>>>(ei, E, M);
    scan_kernel<<<1, 1024, 0, s1>>>();
    dis_kernel<<<node_blocks, TB, 0, s1>>>(NPAD);
    scatter_kernel<<<edge_blocks, TB, 0, s1>>>(ei, E, M);
    cudaEventRecord(evB, s1);

    for (int l = 0; l < L; l++) {
        split_w_kernel<<<w_blocks, TB, 0, s2>>>(gcn_W  + (size_t)l * HDIM * HDIM, 1 + l, 0);
        split_w_kernel<<<w_blocks, TB, 0, s2>>>(skip_W + (size_t)l * HDIM * HDIM, 1 + l, 128);
    }
    cudaEventRecord(evW, s2);

    // ---- main chain on stream 0 ----
    split_w_kernel<<<w_blocks, TB>>>(W_pre, 0, 0);
    split_x_kernel<<<nt_blocks, TB>>>(x, M, ntot);
    wmma_gemm<128, 0><<<gemm_blocks, 512, PRE_SMEM>>>(0, b_pre);   // fused bias+mish+split

    cudaStreamWaitEvent(0, evW, 0);    // layer weights ready
    for (int l = 0; l < L; l++) {
        const float* gb = gcn_b  + (size_t)l * HDIM;
        const float* sb = skip_b + (size_t)l * HDIM;
        wmma_gemm<256, 1><<<gemm_blocks, 512, FUSED_SMEM>>>(1 + l, nullptr);
        if (l == 0) cudaStreamWaitEvent(0, evB, 0);   // CSR ready before first agg
        if (l == L - 1)
            csr_agg_kernel<true><<<post_blocks, TB>>>(gb, sb, W_post, b_post, out, M);
        else
            csr_agg_kernel<false><<<aggw_blocks, TB>>>(gb, sb, nullptr, nullptr, nullptr, M);
    }
}